// round 2
// baseline (speedup 1.0000x reference)
#include <cuda_runtime.h>
#include <cstddef>

// ---------------------------------------------------------------------------
// Problem constants (fixed by the dataset)
// ---------------------------------------------------------------------------
#define NPAPER  100000
#define NAUTHOR 50000
#define NEDGE   600000
#define HD      128

// ---------------------------------------------------------------------------
// Static scratch (no allocations allowed)
// ---------------------------------------------------------------------------
__device__ float g_yp0[(size_t)NPAPER * HD];
__device__ float g_yp1[(size_t)NPAPER * HD];
__device__ float g_ya0[(size_t)NAUTHOR * HD];
__device__ float g_ya1[(size_t)NAUTHOR * HD];
__device__ float g_mp1[(size_t)NPAPER * HD];   // m_a2p accumulator
__device__ float g_mp2[(size_t)NPAPER * HD];   // m_p2p accumulator
__device__ float g_ma [(size_t)NAUTHOR * HD];  // m_p2a accumulator
__device__ float g_inv_a2p[NPAPER];
__device__ float g_inv_p2a[NAUTHOR];
__device__ float g_inv_p2p[NPAPER];
__device__ float g_wsum[2 * HD * HD];          // Wr[l,0]+Wr[l,2]

// ---------------------------------------------------------------------------
// Utility kernels
// ---------------------------------------------------------------------------
__global__ void zero_kernel(float4* __restrict__ p, int n4) {
    int stride = gridDim.x * blockDim.x;
    for (int i = blockIdx.x * blockDim.x + threadIdx.x; i < n4; i += stride)
        p[i] = make_float4(0.f, 0.f, 0.f, 0.f);
}

__global__ void count_deg_kernel(const int* __restrict__ dst, float* __restrict__ deg, int n) {
    int i = blockIdx.x * blockDim.x + threadIdx.x;
    if (i < n) atomicAdd(&deg[dst[i]], 1.0f);
}

__global__ void recip_kernel(float* __restrict__ p, int n) {
    int i = blockIdx.x * blockDim.x + threadIdx.x;
    if (i < n) p[i] = 1.0f / fmaxf(p[i], 1.0f);
}

// ws[l] = Wr[l,0] + Wr[l,2]
__global__ void wsum_kernel(const float* __restrict__ Wr, float* __restrict__ ws) {
    int i = blockIdx.x * blockDim.x + threadIdx.x;
    const int T = 2 * HD * HD;
    if (i < T) {
        int l = i / (HD * HD);
        int o = i - l * (HD * HD);
        ws[i] = Wr[(l * 3 + 0) * HD * HD + o] + Wr[(l * 3 + 2) * HD * HD + o];
    }
}

// ---------------------------------------------------------------------------
// Edge scatter: one warp per edge. Gather 128 floats of feat[src], vector-RED
// into acc[dst]. Feature tables are L2-resident (<= 51 MB).
// ---------------------------------------------------------------------------
__global__ void scatter_kernel(const float4* __restrict__ feat,
                               const int* __restrict__ src,
                               const int* __restrict__ dst,
                               float4* __restrict__ acc, int n) {
    int t = blockIdx.x * blockDim.x + threadIdx.x;
    int e = t >> 5;
    int lane = t & 31;
    if (e >= n) return;
    int s = __ldg(&src[e]);
    int d = __ldg(&dst[e]);
    float4 v = feat[(size_t)s * 32 + lane];
    float4* p = acc + (size_t)d * 32 + lane;
    asm volatile("red.global.add.v4.f32 [%0], {%1, %2, %3, %4};"
                 :: "l"(p), "f"(v.x), "f"(v.y), "f"(v.z), "f"(v.w) : "memory");
}

// ---------------------------------------------------------------------------
// SIMT GEMM, N = 128, any K multiple of 16.  CTA = 256 threads computes a
// 64-row x 128-col tile; thread (tx in [0,32), ty in [0,8)) owns 8 rows x
// 4 cols (float4 columns).  W tile stays in smem; A-row reads are warp
// broadcasts.  Inner loop is 32 FFMA per 9 LDS -> FMA-pipe bound.
// ---------------------------------------------------------------------------
__global__ __launch_bounds__(256)
void gemm_n128(const float* __restrict__ A, int M, int K,
               const float* __restrict__ W, const float* __restrict__ bias,
               float* __restrict__ Y, int relu) {
    __shared__ float As[64][16];
    __shared__ float Ws[16][128];
    int tid = threadIdx.x;
    int tx = tid & 31;
    int ty = tid >> 5;
    int rowBase = blockIdx.x * 64;
    float acc[8][4] = {};

    int rL = tid >> 2, q = tid & 3;
    int rowL = rowBase + rL; if (rowL > M - 1) rowL = M - 1;

    for (int k0 = 0; k0 < K; k0 += 16) {
        *(float4*)&As[rL][q * 4] =
            *(const float4*)(A + (size_t)rowL * K + k0 + q * 4);
#pragma unroll
        for (int j = 0; j < 2; j++) {
            int i = tid + j * 256;
            int k = i >> 5, c = i & 31;
            *(float4*)&Ws[k][c * 4] =
                *(const float4*)(W + (size_t)(k0 + k) * 128 + c * 4);
        }
        __syncthreads();
#pragma unroll
        for (int k = 0; k < 16; k++) {
            float4 wv = *(float4*)&Ws[k][tx * 4];
#pragma unroll
            for (int r = 0; r < 8; r++) {
                float a = As[ty * 8 + r][k];
                acc[r][0] += a * wv.x; acc[r][1] += a * wv.y;
                acc[r][2] += a * wv.z; acc[r][3] += a * wv.w;
            }
        }
        __syncthreads();
    }

    float4 bv = *(const float4*)(bias + tx * 4);
#pragma unroll
    for (int r = 0; r < 8; r++) {
        int row = rowBase + ty * 8 + r;
        if (row < M) {
            float4 o;
            o.x = acc[r][0] + bv.x; o.y = acc[r][1] + bv.y;
            o.z = acc[r][2] + bv.z; o.w = acc[r][3] + bv.w;
            if (relu) {
                o.x = fmaxf(o.x, 0.f); o.y = fmaxf(o.y, 0.f);
                o.z = fmaxf(o.z, 0.f); o.w = fmaxf(o.w, 0.f);
            }
            *(float4*)(Y + (size_t)row * 128 + tx * 4) = o;
        }
    }
}

// ---------------------------------------------------------------------------
// Fused multi-input GEMM: Y = sum_s (A_s * scale_s) @ W_s + b0 (+ b1).
// Each input has K = 128.  Per-row scale (inverse degree) folds the
// segment-mean divide into the A-tile load.  nIn in {2, 3}.
// ---------------------------------------------------------------------------
__global__ __launch_bounds__(256)
void gemm_multi128(const float* __restrict__ A0, const float* __restrict__ s0, const float* __restrict__ W0,
                   const float* __restrict__ A1, const float* __restrict__ s1, const float* __restrict__ W1,
                   const float* __restrict__ A2, const float* __restrict__ s2, const float* __restrict__ W2,
                   int nIn, int M,
                   const float* __restrict__ b0, const float* __restrict__ b1,
                   float* __restrict__ Y) {
    const float* Aar[3] = {A0, A1, A2};
    const float* Sar[3] = {s0, s1, s2};
    const float* War[3] = {W0, W1, W2};
    __shared__ float As[64][16];
    __shared__ float Ws[16][128];
    int tid = threadIdx.x;
    int tx = tid & 31;
    int ty = tid >> 5;
    int rowBase = blockIdx.x * 64;
    float acc[8][4] = {};

    int rL = tid >> 2, q = tid & 3;
    int rowL = rowBase + rL; if (rowL > M - 1) rowL = M - 1;

    for (int s = 0; s < nIn; s++) {
        const float* A = Aar[s];
        const float* SC = Sar[s];
        const float* W = War[s];
        float scale = SC ? SC[rowL] : 1.0f;
        for (int k0 = 0; k0 < 128; k0 += 16) {
            float4 av = *(const float4*)(A + (size_t)rowL * 128 + k0 + q * 4);
            av.x *= scale; av.y *= scale; av.z *= scale; av.w *= scale;
            *(float4*)&As[rL][q * 4] = av;
#pragma unroll
            for (int j = 0; j < 2; j++) {
                int i = tid + j * 256;
                int k = i >> 5, c = i & 31;
                *(float4*)&Ws[k][c * 4] =
                    *(const float4*)(W + (size_t)(k0 + k) * 128 + c * 4);
            }
            __syncthreads();
#pragma unroll
            for (int k = 0; k < 16; k++) {
                float4 wv = *(float4*)&Ws[k][tx * 4];
#pragma unroll
                for (int r = 0; r < 8; r++) {
                    float a = As[ty * 8 + r][k];
                    acc[r][0] += a * wv.x; acc[r][1] += a * wv.y;
                    acc[r][2] += a * wv.z; acc[r][3] += a * wv.w;
                }
            }
            __syncthreads();
        }
    }

    float4 bv = *(const float4*)(b0 + tx * 4);
    if (b1) {
        float4 b2 = *(const float4*)(b1 + tx * 4);
        bv.x += b2.x; bv.y += b2.y; bv.z += b2.z; bv.w += b2.w;
    }
#pragma unroll
    for (int r = 0; r < 8; r++) {
        int row = rowBase + ty * 8 + r;
        if (row < M) {
            float4 o;
            o.x = acc[r][0] + bv.x; o.y = acc[r][1] + bv.y;
            o.z = acc[r][2] + bv.z; o.w = acc[r][3] + bv.w;
            *(float4*)(Y + (size_t)row * 128 + tx * 4) = o;
        }
    }
}

// ---------------------------------------------------------------------------
// Final classifier GEMM: [M,128] @ [128,64] + b.  CTA = 256 threads computes
// 64 rows x 64 cols; thread (tx in [0,16), ty in [0,16)) owns 4 rows x 4 cols.
// ---------------------------------------------------------------------------
__global__ __launch_bounds__(256)
void gemm_n64(const float* __restrict__ A, int M,
              const float* __restrict__ W, const float* __restrict__ bias,
              float* __restrict__ Y) {
    __shared__ float As[64][16];
    __shared__ float Ws[16][64];
    int tid = threadIdx.x;
    int tx = tid & 15;
    int ty = tid >> 4;
    int rowBase = blockIdx.x * 64;
    float acc[4][4] = {};

    int rL = tid >> 2, q = tid & 3;
    int rowL = rowBase + rL; if (rowL > M - 1) rowL = M - 1;

    for (int k0 = 0; k0 < 128; k0 += 16) {
        *(float4*)&As[rL][q * 4] =
            *(const float4*)(A + (size_t)rowL * 128 + k0 + q * 4);
        {
            int k = tid >> 4, c = tid & 15;  // 256 threads = 256 float4 = 16x64 tile
            *(float4*)&Ws[k][c * 4] =
                *(const float4*)(W + (size_t)(k0 + k) * 64 + c * 4);
        }
        __syncthreads();
#pragma unroll
        for (int k = 0; k < 16; k++) {
            float4 wv = *(float4*)&Ws[k][tx * 4];
#pragma unroll
            for (int r = 0; r < 4; r++) {
                float a = As[ty * 4 + r][k];
                acc[r][0] += a * wv.x; acc[r][1] += a * wv.y;
                acc[r][2] += a * wv.z; acc[r][3] += a * wv.w;
            }
        }
        __syncthreads();
    }

    float4 bv = *(const float4*)(bias + tx * 4);
#pragma unroll
    for (int r = 0; r < 4; r++) {
        int row = rowBase + ty * 4 + r;
        if (row < M) {
            float4 o;
            o.x = acc[r][0] + bv.x; o.y = acc[r][1] + bv.y;
            o.z = acc[r][2] + bv.z; o.w = acc[r][3] + bv.w;
            *(float4*)(Y + (size_t)row * 64 + tx * 4) = o;
        }
    }
}

// ---------------------------------------------------------------------------
// Orchestration
// ---------------------------------------------------------------------------
extern "C" void kernel_launch(void* const* d_in, const int* in_sizes, int n_in,
                              void* d_out, int out_size) {
    const float* x_paper  = (const float*)d_in[0];
    const float* x_author = (const float*)d_in[1];
    const float* lin_p_w  = (const float*)d_in[2];
    const float* lin_p_b  = (const float*)d_in[3];
    const float* lin_a_w  = (const float*)d_in[4];
    const float* lin_a_b  = (const float*)d_in[5];
    const float* Wl       = (const float*)d_in[6];
    const float* bl       = (const float*)d_in[7];
    const float* Wr       = (const float*)d_in[8];
    const float* lin_w    = (const float*)d_in[9];
    const float* lin_b    = (const float*)d_in[10];
    const int* a2p_src = (const int*)d_in[11];
    const int* a2p_dst = (const int*)d_in[12];
    const int* p2a_src = (const int*)d_in[13];
    const int* p2a_dst = (const int*)d_in[14];
    const int* p2p_src = (const int*)d_in[15];
    const int* p2p_dst = (const int*)d_in[16];
    float* out = (float*)d_out;

    float *yp0, *yp1, *ya0, *ya1, *mp1, *mp2, *ma, *iv1, *iv2, *iv3, *wsum;
    cudaGetSymbolAddress((void**)&yp0, g_yp0);
    cudaGetSymbolAddress((void**)&yp1, g_yp1);
    cudaGetSymbolAddress((void**)&ya0, g_ya0);
    cudaGetSymbolAddress((void**)&ya1, g_ya1);
    cudaGetSymbolAddress((void**)&mp1, g_mp1);
    cudaGetSymbolAddress((void**)&mp2, g_mp2);
    cudaGetSymbolAddress((void**)&ma,  g_ma);
    cudaGetSymbolAddress((void**)&iv1, g_inv_a2p);
    cudaGetSymbolAddress((void**)&iv2, g_inv_p2a);
    cudaGetSymbolAddress((void**)&iv3, g_inv_p2p);
    cudaGetSymbolAddress((void**)&wsum, g_wsum);

    const int ZG = 2048;

    // --- inverse degrees (same for both layers) ---
    zero_kernel<<<ZG, 256>>>((float4*)iv1, NPAPER / 4);
    zero_kernel<<<ZG, 256>>>((float4*)iv2, NAUTHOR / 4);
    zero_kernel<<<ZG, 256>>>((float4*)iv3, NPAPER / 4);
    count_deg_kernel<<<(NEDGE + 255) / 256, 256>>>(a2p_dst, iv1, NEDGE);
    count_deg_kernel<<<(NEDGE + 255) / 256, 256>>>(p2a_dst, iv2, NEDGE);
    count_deg_kernel<<<(NEDGE + 255) / 256, 256>>>(p2p_dst, iv3, NEDGE);
    recip_kernel<<<(NPAPER + 255) / 256, 256>>>(iv1, NPAPER);
    recip_kernel<<<(NAUTHOR + 255) / 256, 256>>>(iv2, NAUTHOR);
    recip_kernel<<<(NPAPER + 255) / 256, 256>>>(iv3, NPAPER);

    // --- Wr[l,0] + Wr[l,2] ---
    wsum_kernel<<<(2 * HD * HD + 255) / 256, 256>>>(Wr, wsum);

    // --- input projections + relu ---
    gemm_n128<<<(NPAPER + 63) / 64, 256>>>(x_paper, NPAPER, 256, lin_p_w, lin_p_b, yp0, 1);
    gemm_n128<<<(NAUTHOR + 63) / 64, 256>>>(x_author, NAUTHOR, 128, lin_a_w, lin_a_b, ya0, 1);

    float *ypc = yp0, *ypn = yp1, *yac = ya0, *yan = ya1;
    const int SG = (NEDGE * 32 + 255) / 256;  // warp per edge

    for (int l = 0; l < 2; l++) {
        zero_kernel<<<ZG, 256>>>((float4*)mp1, NPAPER * HD / 4);
        zero_kernel<<<ZG, 256>>>((float4*)mp2, NPAPER * HD / 4);
        zero_kernel<<<ZG, 256>>>((float4*)ma,  NAUTHOR * HD / 4);

        scatter_kernel<<<SG, 256>>>((const float4*)yac, a2p_src, a2p_dst, (float4*)mp1, NEDGE);
        scatter_kernel<<<SG, 256>>>((const float4*)ypc, p2p_src, p2p_dst, (float4*)mp2, NEDGE);
        scatter_kernel<<<SG, 256>>>((const float4*)ypc, p2a_src, p2a_dst, (float4*)ma,  NEDGE);

        // new_p = (m_a2p/deg)@Wl[l,0] + (m_p2p/deg)@Wl[l,2] + yp@(Wr[l,0]+Wr[l,2]) + bl[l,0]+bl[l,2]
        gemm_multi128<<<(NPAPER + 63) / 64, 256>>>(
            mp1, iv1, Wl + (size_t)(l * 3 + 0) * HD * HD,
            mp2, iv3, Wl + (size_t)(l * 3 + 2) * HD * HD,
            ypc, nullptr, wsum + (size_t)l * HD * HD,
            3, NPAPER,
            bl + (size_t)(l * 3 + 0) * HD, bl + (size_t)(l * 3 + 2) * HD,
            ypn);

        // new_a = (m_p2a/deg)@Wl[l,1] + ya@Wr[l,1] + bl[l,1]
        gemm_multi128<<<(NAUTHOR + 63) / 64, 256>>>(
            ma, iv2, Wl + (size_t)(l * 3 + 1) * HD * HD,
            yac, nullptr, Wr + (size_t)(l * 3 + 1) * HD * HD,
            nullptr, nullptr, nullptr,
            2, NAUTHOR,
            bl + (size_t)(l * 3 + 1) * HD, nullptr,
            yan);

        float* t;
        t = ypc; ypc = ypn; ypn = t;
        t = yac; yac = yan; yan = t;
    }

    // --- final classifier on papers ---
    gemm_n64<<<(NPAPER + 63) / 64, 256>>>(ypc, NPAPER, lin_w, lin_b, out);
}

// round 4
// speedup vs baseline: 1.0976x; 1.0976x over previous
#include <cuda_runtime.h>
#include <cstddef>

// ---------------------------------------------------------------------------
// Problem constants (fixed by the dataset)
// ---------------------------------------------------------------------------
#define NPAPER  100000
#define NAUTHOR 50000
#define NEDGE   600000
#define HD      128

typedef unsigned long long u64;

// ---------------------------------------------------------------------------
// Static scratch (no allocations allowed)
// ---------------------------------------------------------------------------
__device__ float g_yp0[(size_t)NPAPER * HD];
__device__ float g_yp1[(size_t)NPAPER * HD];
__device__ float g_ya0[(size_t)NAUTHOR * HD];
__device__ float g_ya1[(size_t)NAUTHOR * HD];
__device__ float g_mp1[(size_t)NPAPER * HD];   // m_a2p accumulator
__device__ float g_mp2[(size_t)NPAPER * HD];   // m_p2p accumulator
__device__ float g_ma [(size_t)NAUTHOR * HD];  // m_p2a accumulator
__device__ float g_inv_a2p[NPAPER];
__device__ float g_inv_p2a[NAUTHOR];
__device__ float g_inv_p2p[NPAPER];
__device__ float g_wsum[2 * HD * HD];          // Wr[l,0]+Wr[l,2]

// ---------------------------------------------------------------------------
// f32x2 packed-FMA helpers (Blackwell; ptxas never emits FFMA2 from C++)
// ---------------------------------------------------------------------------
__device__ __forceinline__ u64 fma2(u64 a, u64 b, u64 c) {
    u64 d;
    asm("fma.rn.f32x2 %0, %1, %2, %3;" : "=l"(d) : "l"(a), "l"(b), "l"(c));
    return d;
}
__device__ __forceinline__ u64 dup2(float w) {
    u64 d;
    asm("mov.b64 %0, {%1, %1};" : "=l"(d) : "f"(w));
    return d;
}
__device__ __forceinline__ float lo32(u64 v) { return __uint_as_float((unsigned)v); }
__device__ __forceinline__ float hi32(u64 v) { return __uint_as_float((unsigned)(v >> 32)); }

// ---------------------------------------------------------------------------
// Utility kernels
// ---------------------------------------------------------------------------
__global__ void zero_kernel(float4* __restrict__ p, int n4) {
    int stride = gridDim.x * blockDim.x;
    for (int i = blockIdx.x * blockDim.x + threadIdx.x; i < n4; i += stride)
        p[i] = make_float4(0.f, 0.f, 0.f, 0.f);
}

__global__ void count_deg_kernel(const int* __restrict__ dst, float* __restrict__ deg, int n) {
    int i = blockIdx.x * blockDim.x + threadIdx.x;
    if (i < n) atomicAdd(&deg[dst[i]], 1.0f);
}

__global__ void recip_kernel(float* __restrict__ p, int n) {
    int i = blockIdx.x * blockDim.x + threadIdx.x;
    if (i < n) p[i] = 1.0f / fmaxf(p[i], 1.0f);
}

// ws[l] = Wr[l,0] + Wr[l,2]
__global__ void wsum_kernel(const float* __restrict__ Wr, float* __restrict__ ws) {
    int i = blockIdx.x * blockDim.x + threadIdx.x;
    const int T = 2 * HD * HD;
    if (i < T) {
        int l = i / (HD * HD);
        int o = i - l * (HD * HD);
        ws[i] = Wr[(l * 3 + 0) * HD * HD + o] + Wr[(l * 3 + 2) * HD * HD + o];
    }
}

// ---------------------------------------------------------------------------
// Edge scatter: one warp per edge. Gather 128 floats of feat[src], vector-RED
// into acc[dst]. Feature tables are L2-resident.
// ---------------------------------------------------------------------------
__global__ void scatter_kernel(const float4* __restrict__ feat,
                               const int* __restrict__ src,
                               const int* __restrict__ dst,
                               float4* __restrict__ acc, int n) {
    int t = blockIdx.x * blockDim.x + threadIdx.x;
    int e = t >> 5;
    int lane = t & 31;
    if (e >= n) return;
    int s = __ldg(&src[e]);
    int d = __ldg(&dst[e]);
    float4 v = feat[(size_t)s * 32 + lane];
    float4* p = acc + (size_t)d * 32 + lane;
    asm volatile("red.global.add.v4.f32 [%0], {%1, %2, %3, %4};"
                 :: "l"(p), "f"(v.x), "f"(v.y), "f"(v.z), "f"(v.w) : "memory");
}

// ---------------------------------------------------------------------------
// f32x2 SIMT GEMM, N = 128.  CTA = 256 threads, tile 64 rows x 128 cols.
// A staged k-major (AsT[k][row], pad 68) so one LDS.128 yields 4 rows = two
// f32x2 pairs.  W broadcast-dup'd into f32x2 via mov.b64.  16 FFMA2/k.
// ---------------------------------------------------------------------------
__global__ __launch_bounds__(256)
void gemm_n128(const float* __restrict__ A, int M, int K,
               const float* __restrict__ W, const float* __restrict__ bias,
               float* __restrict__ Y, int relu) {
    __shared__ float AsT[16][68];
    __shared__ float Ws[16][128];
    int tid = threadIdx.x;
    int tx = tid & 31;           // col group: cols 4tx..4tx+3
    int ty = tid >> 5;           // rows ty*8..ty*8+7
    int rowBase = blockIdx.x * 64;
    u64 acc[4][4] = {};          // acc[p][c] packs rows (2p, 2p+1), col c

    int rL = tid >> 2, q = tid & 3;
    int rowL = rowBase + rL; if (rowL > M - 1) rowL = M - 1;

    for (int k0 = 0; k0 < K; k0 += 16) {
        float4 av = *(const float4*)(A + (size_t)rowL * K + k0 + q * 4);
        AsT[q * 4 + 0][rL] = av.x;
        AsT[q * 4 + 1][rL] = av.y;
        AsT[q * 4 + 2][rL] = av.z;
        AsT[q * 4 + 3][rL] = av.w;
#pragma unroll
        for (int j = 0; j < 2; j++) {
            int i = tid + j * 256;
            int k = i >> 5, c = i & 31;
            *(float4*)&Ws[k][c * 4] =
                *(const float4*)(W + (size_t)(k0 + k) * 128 + c * 4);
        }
        __syncthreads();
#pragma unroll
        for (int k = 0; k < 16; k++) {
            ulonglong2 a01 = *(const ulonglong2*)&AsT[k][ty * 8];
            ulonglong2 a23 = *(const ulonglong2*)&AsT[k][ty * 8 + 4];
            float4 wv = *(float4*)&Ws[k][tx * 4];
            u64 w0 = dup2(wv.x), w1 = dup2(wv.y), w2 = dup2(wv.z), w3 = dup2(wv.w);
            acc[0][0] = fma2(a01.x, w0, acc[0][0]);
            acc[0][1] = fma2(a01.x, w1, acc[0][1]);
            acc[0][2] = fma2(a01.x, w2, acc[0][2]);
            acc[0][3] = fma2(a01.x, w3, acc[0][3]);
            acc[1][0] = fma2(a01.y, w0, acc[1][0]);
            acc[1][1] = fma2(a01.y, w1, acc[1][1]);
            acc[1][2] = fma2(a01.y, w2, acc[1][2]);
            acc[1][3] = fma2(a01.y, w3, acc[1][3]);
            acc[2][0] = fma2(a23.x, w0, acc[2][0]);
            acc[2][1] = fma2(a23.x, w1, acc[2][1]);
            acc[2][2] = fma2(a23.x, w2, acc[2][2]);
            acc[2][3] = fma2(a23.x, w3, acc[2][3]);
            acc[3][0] = fma2(a23.y, w0, acc[3][0]);
            acc[3][1] = fma2(a23.y, w1, acc[3][1]);
            acc[3][2] = fma2(a23.y, w2, acc[3][2]);
            acc[3][3] = fma2(a23.y, w3, acc[3][3]);
        }
        __syncthreads();
    }

    float4 bv = *(const float4*)(bias + tx * 4);
#pragma unroll
    for (int p = 0; p < 4; p++) {
#pragma unroll
        for (int h = 0; h < 2; h++) {
            int row = rowBase + ty * 8 + p * 2 + h;
            if (row < M) {
                float4 o;
                o.x = (h ? hi32(acc[p][0]) : lo32(acc[p][0])) + bv.x;
                o.y = (h ? hi32(acc[p][1]) : lo32(acc[p][1])) + bv.y;
                o.z = (h ? hi32(acc[p][2]) : lo32(acc[p][2])) + bv.z;
                o.w = (h ? hi32(acc[p][3]) : lo32(acc[p][3])) + bv.w;
                if (relu) {
                    o.x = fmaxf(o.x, 0.f); o.y = fmaxf(o.y, 0.f);
                    o.z = fmaxf(o.z, 0.f); o.w = fmaxf(o.w, 0.f);
                }
                *(float4*)(Y + (size_t)row * 128 + tx * 4) = o;
            }
        }
    }
}

// ---------------------------------------------------------------------------
// Fused multi-input f32x2 GEMM: Y = sum_s (A_s * scale_s) @ W_s + b0 (+ b1).
// Each input K = 128.  Per-row inverse-degree folds the mean into the A load.
// ---------------------------------------------------------------------------
__global__ __launch_bounds__(256)
void gemm_multi128(const float* __restrict__ A0, const float* __restrict__ s0, const float* __restrict__ W0,
                   const float* __restrict__ A1, const float* __restrict__ s1, const float* __restrict__ W1,
                   const float* __restrict__ A2, const float* __restrict__ s2, const float* __restrict__ W2,
                   int nIn, int M,
                   const float* __restrict__ b0, const float* __restrict__ b1,
                   float* __restrict__ Y) {
    const float* Aar[3] = {A0, A1, A2};
    const float* Sar[3] = {s0, s1, s2};
    const float* War[3] = {W0, W1, W2};
    __shared__ float AsT[16][68];
    __shared__ float Ws[16][128];
    int tid = threadIdx.x;
    int tx = tid & 31;
    int ty = tid >> 5;
    int rowBase = blockIdx.x * 64;
    u64 acc[4][4] = {};

    int rL = tid >> 2, q = tid & 3;
    int rowL = rowBase + rL; if (rowL > M - 1) rowL = M - 1;

    for (int s = 0; s < nIn; s++) {
        const float* A = Aar[s];
        const float* SC = Sar[s];
        const float* W = War[s];
        float scale = SC ? SC[rowL] : 1.0f;
        for (int k0 = 0; k0 < 128; k0 += 16) {
            float4 av = *(const float4*)(A + (size_t)rowL * 128 + k0 + q * 4);
            AsT[q * 4 + 0][rL] = av.x * scale;
            AsT[q * 4 + 1][rL] = av.y * scale;
            AsT[q * 4 + 2][rL] = av.z * scale;
            AsT[q * 4 + 3][rL] = av.w * scale;
#pragma unroll
            for (int j = 0; j < 2; j++) {
                int i = tid + j * 256;
                int k = i >> 5, c = i & 31;
                *(float4*)&Ws[k][c * 4] =
                    *(const float4*)(W + (size_t)(k0 + k) * 128 + c * 4);
            }
            __syncthreads();
#pragma unroll
            for (int k = 0; k < 16; k++) {
                ulonglong2 a01 = *(const ulonglong2*)&AsT[k][ty * 8];
                ulonglong2 a23 = *(const ulonglong2*)&AsT[k][ty * 8 + 4];
                float4 wv = *(float4*)&Ws[k][tx * 4];
                u64 w0 = dup2(wv.x), w1 = dup2(wv.y), w2 = dup2(wv.z), w3 = dup2(wv.w);
                acc[0][0] = fma2(a01.x, w0, acc[0][0]);
                acc[0][1] = fma2(a01.x, w1, acc[0][1]);
                acc[0][2] = fma2(a01.x, w2, acc[0][2]);
                acc[0][3] = fma2(a01.x, w3, acc[0][3]);
                acc[1][0] = fma2(a01.y, w0, acc[1][0]);
                acc[1][1] = fma2(a01.y, w1, acc[1][1]);
                acc[1][2] = fma2(a01.y, w2, acc[1][2]);
                acc[1][3] = fma2(a01.y, w3, acc[1][3]);
                acc[2][0] = fma2(a23.x, w0, acc[2][0]);
                acc[2][1] = fma2(a23.x, w1, acc[2][1]);
                acc[2][2] = fma2(a23.x, w2, acc[2][2]);
                acc[2][3] = fma2(a23.x, w3, acc[2][3]);
                acc[3][0] = fma2(a23.y, w0, acc[3][0]);
                acc[3][1] = fma2(a23.y, w1, acc[3][1]);
                acc[3][2] = fma2(a23.y, w2, acc[3][2]);
                acc[3][3] = fma2(a23.y, w3, acc[3][3]);
            }
            __syncthreads();
        }
    }

    float4 bv = *(const float4*)(b0 + tx * 4);
    if (b1) {
        float4 b2 = *(const float4*)(b1 + tx * 4);
        bv.x += b2.x; bv.y += b2.y; bv.z += b2.z; bv.w += b2.w;
    }
#pragma unroll
    for (int p = 0; p < 4; p++) {
#pragma unroll
        for (int h = 0; h < 2; h++) {
            int row = rowBase + ty * 8 + p * 2 + h;
            if (row < M) {
                float4 o;
                o.x = (h ? hi32(acc[p][0]) : lo32(acc[p][0])) + bv.x;
                o.y = (h ? hi32(acc[p][1]) : lo32(acc[p][1])) + bv.y;
                o.z = (h ? hi32(acc[p][2]) : lo32(acc[p][2])) + bv.z;
                o.w = (h ? hi32(acc[p][3]) : lo32(acc[p][3])) + bv.w;
                *(float4*)(Y + (size_t)row * 128 + tx * 4) = o;
            }
        }
    }
}

// ---------------------------------------------------------------------------
// Final classifier GEMM (f32x2): [M,128] @ [128,64] + b.  Tile 64x64.
// tx in [0,16) owns cols 4tx..4tx+3; ty in [0,16) owns rows 4ty..4ty+3.
// ---------------------------------------------------------------------------
__global__ __launch_bounds__(256)
void gemm_n64(const float* __restrict__ A, int M,
              const float* __restrict__ W, const float* __restrict__ bias,
              float* __restrict__ Y) {
    __shared__ float AsT[16][68];
    __shared__ float Ws[16][64];
    int tid = threadIdx.x;
    int tx = tid & 15;
    int ty = tid >> 4;
    int rowBase = blockIdx.x * 64;
    u64 acc[2][4] = {};

    int rL = tid >> 2, q = tid & 3;
    int rowL = rowBase + rL; if (rowL > M - 1) rowL = M - 1;

    for (int k0 = 0; k0 < 128; k0 += 16) {
        float4 av = *(const float4*)(A + (size_t)rowL * 128 + k0 + q * 4);
        AsT[q * 4 + 0][rL] = av.x;
        AsT[q * 4 + 1][rL] = av.y;
        AsT[q * 4 + 2][rL] = av.z;
        AsT[q * 4 + 3][rL] = av.w;
        {
            int k = tid >> 4, c = tid & 15;
            *(float4*)&Ws[k][c * 4] =
                *(const float4*)(W + (size_t)(k0 + k) * 64 + c * 4);
        }
        __syncthreads();
#pragma unroll
        for (int k = 0; k < 16; k++) {
            ulonglong2 a01 = *(const ulonglong2*)&AsT[k][ty * 4];
            float4 wv = *(float4*)&Ws[k][tx * 4];
            u64 w0 = dup2(wv.x), w1 = dup2(wv.y), w2 = dup2(wv.z), w3 = dup2(wv.w);
            acc[0][0] = fma2(a01.x, w0, acc[0][0]);
            acc[0][1] = fma2(a01.x, w1, acc[0][1]);
            acc[0][2] = fma2(a01.x, w2, acc[0][2]);
            acc[0][3] = fma2(a01.x, w3, acc[0][3]);
            acc[1][0] = fma2(a01.y, w0, acc[1][0]);
            acc[1][1] = fma2(a01.y, w1, acc[1][1]);
            acc[1][2] = fma2(a01.y, w2, acc[1][2]);
            acc[1][3] = fma2(a01.y, w3, acc[1][3]);
        }
        __syncthreads();
    }

    float4 bv = *(const float4*)(bias + tx * 4);
#pragma unroll
    for (int p = 0; p < 2; p++) {
#pragma unroll
        for (int h = 0; h < 2; h++) {
            int row = rowBase + ty * 4 + p * 2 + h;
            if (row < M) {
                float4 o;
                o.x = (h ? hi32(acc[p][0]) : lo32(acc[p][0])) + bv.x;
                o.y = (h ? hi32(acc[p][1]) : lo32(acc[p][1])) + bv.y;
                o.z = (h ? hi32(acc[p][2]) : lo32(acc[p][2])) + bv.z;
                o.w = (h ? hi32(acc[p][3]) : lo32(acc[p][3])) + bv.w;
                *(float4*)(Y + (size_t)row * 64 + tx * 4) = o;
            }
        }
    }
}

// ---------------------------------------------------------------------------
// Orchestration
// ---------------------------------------------------------------------------
extern "C" void kernel_launch(void* const* d_in, const int* in_sizes, int n_in,
                              void* d_out, int out_size) {
    const float* x_paper  = (const float*)d_in[0];
    const float* x_author = (const float*)d_in[1];
    const float* lin_p_w  = (const float*)d_in[2];
    const float* lin_p_b  = (const float*)d_in[3];
    const float* lin_a_w  = (const float*)d_in[4];
    const float* lin_a_b  = (const float*)d_in[5];
    const float* Wl       = (const float*)d_in[6];
    const float* bl       = (const float*)d_in[7];
    const float* Wr       = (const float*)d_in[8];
    const float* lin_w    = (const float*)d_in[9];
    const float* lin_b    = (const float*)d_in[10];
    const int* a2p_src = (const int*)d_in[11];
    const int* a2p_dst = (const int*)d_in[12];
    const int* p2a_src = (const int*)d_in[13];
    const int* p2a_dst = (const int*)d_in[14];
    const int* p2p_src = (const int*)d_in[15];
    const int* p2p_dst = (const int*)d_in[16];
    float* out = (float*)d_out;

    float *yp0, *yp1, *ya0, *ya1, *mp1, *mp2, *ma, *iv1, *iv2, *iv3, *wsum;
    cudaGetSymbolAddress((void**)&yp0, g_yp0);
    cudaGetSymbolAddress((void**)&yp1, g_yp1);
    cudaGetSymbolAddress((void**)&ya0, g_ya0);
    cudaGetSymbolAddress((void**)&ya1, g_ya1);
    cudaGetSymbolAddress((void**)&mp1, g_mp1);
    cudaGetSymbolAddress((void**)&mp2, g_mp2);
    cudaGetSymbolAddress((void**)&ma,  g_ma);
    cudaGetSymbolAddress((void**)&iv1, g_inv_a2p);
    cudaGetSymbolAddress((void**)&iv2, g_inv_p2a);
    cudaGetSymbolAddress((void**)&iv3, g_inv_p2p);
    cudaGetSymbolAddress((void**)&wsum, g_wsum);

    const int ZG = 2048;

    // --- inverse degrees (same for both layers) ---
    zero_kernel<<<ZG, 256>>>((float4*)iv1, NPAPER / 4);
    zero_kernel<<<ZG, 256>>>((float4*)iv2, NAUTHOR / 4);
    zero_kernel<<<ZG, 256>>>((float4*)iv3, NPAPER / 4);
    count_deg_kernel<<<(NEDGE + 255) / 256, 256>>>(a2p_dst, iv1, NEDGE);
    count_deg_kernel<<<(NEDGE + 255) / 256, 256>>>(p2a_dst, iv2, NEDGE);
    count_deg_kernel<<<(NEDGE + 255) / 256, 256>>>(p2p_dst, iv3, NEDGE);
    recip_kernel<<<(NPAPER + 255) / 256, 256>>>(iv1, NPAPER);
    recip_kernel<<<(NAUTHOR + 255) / 256, 256>>>(iv2, NAUTHOR);
    recip_kernel<<<(NPAPER + 255) / 256, 256>>>(iv3, NPAPER);

    // --- Wr[l,0] + Wr[l,2] ---
    wsum_kernel<<<(2 * HD * HD + 255) / 256, 256>>>(Wr, wsum);

    // --- input projections + relu ---
    gemm_n128<<<(NPAPER + 63) / 64, 256>>>(x_paper, NPAPER, 256, lin_p_w, lin_p_b, yp0, 1);
    gemm_n128<<<(NAUTHOR + 63) / 64, 256>>>(x_author, NAUTHOR, 128, lin_a_w, lin_a_b, ya0, 1);

    float *ypc = yp0, *ypn = yp1, *yac = ya0, *yan = ya1;
    const int SG = (NEDGE * 32 + 255) / 256;  // warp per edge

    for (int l = 0; l < 2; l++) {
        zero_kernel<<<ZG, 256>>>((float4*)mp1, NPAPER * HD / 4);
        zero_kernel<<<ZG, 256>>>((float4*)mp2, NPAPER * HD / 4);
        zero_kernel<<<ZG, 256>>>((float4*)ma,  NAUTHOR * HD / 4);

        scatter_kernel<<<SG, 256>>>((const float4*)yac, a2p_src, a2p_dst, (float4*)mp1, NEDGE);
        scatter_kernel<<<SG, 256>>>((const float4*)ypc, p2p_src, p2p_dst, (float4*)mp2, NEDGE);
        scatter_kernel<<<SG, 256>>>((const float4*)ypc, p2a_src, p2a_dst, (float4*)ma,  NEDGE);

        // new_p = (m_a2p/deg)@Wl[l,0] + (m_p2p/deg)@Wl[l,2] + yp@(Wr[l,0]+Wr[l,2]) + bl[l,0]+bl[l,2]
        gemm_multi128<<<(NPAPER + 63) / 64, 256>>>(
            mp1, iv1, Wl + (size_t)(l * 3 + 0) * HD * HD,
            mp2, iv3, Wl + (size_t)(l * 3 + 2) * HD * HD,
            ypc, nullptr, wsum + (size_t)l * HD * HD,
            3, NPAPER,
            bl + (size_t)(l * 3 + 0) * HD, bl + (size_t)(l * 3 + 2) * HD,
            ypn);

        // new_a = (m_p2a/deg)@Wl[l,1] + ya@Wr[l,1] + bl[l,1]
        gemm_multi128<<<(NAUTHOR + 63) / 64, 256>>>(
            ma, iv2, Wl + (size_t)(l * 3 + 1) * HD * HD,
            yac, nullptr, Wr + (size_t)(l * 3 + 1) * HD * HD,
            nullptr, nullptr, nullptr,
            2, NAUTHOR,
            bl + (size_t)(l * 3 + 1) * HD, nullptr,
            yan);

        float* t;
        t = ypc; ypc = ypn; ypn = t;
        t = yac; yac = yan; yan = t;
    }

    // --- final classifier on papers ---
    gemm_n64<<<(NPAPER + 63) / 64, 256>>>(ypc, NPAPER, lin_w, lin_b, out);
}

// round 5
// speedup vs baseline: 1.5028x; 1.3692x over previous
#include <cuda_runtime.h>
#include <cstddef>

// ---------------------------------------------------------------------------
// Problem constants (fixed by the dataset)
// ---------------------------------------------------------------------------
#define NPAPER  100000
#define NAUTHOR 50000
#define NEDGE   600000
#define HD      128

typedef unsigned long long u64;

// ---------------------------------------------------------------------------
// Static scratch (no allocations allowed)
// ---------------------------------------------------------------------------
__device__ float g_yp0[(size_t)NPAPER * HD];
__device__ float g_yp1[(size_t)NPAPER * HD];
__device__ float g_ya0[(size_t)NAUTHOR * HD];
__device__ float g_ya1[(size_t)NAUTHOR * HD];
__device__ float g_mp1[(size_t)NPAPER * HD];   // mean a2p
__device__ float g_mp2[(size_t)NPAPER * HD];   // mean p2p
__device__ float g_ma [(size_t)NAUTHOR * HD];  // mean p2a
__device__ float g_wsum[2 * HD * HD];          // Wr[l,0]+Wr[l,2]

// CSR structures (built once per call, reused across both layers)
__device__ int g_rp_a2p[NPAPER + 1];
__device__ int g_rp_p2a[NAUTHOR + 1];
__device__ int g_rp_p2p[NPAPER + 1];
__device__ int g_col_a2p[NEDGE];
__device__ int g_col_p2a[NEDGE];
__device__ int g_col_p2p[NEDGE];
__device__ int g_cnt[NPAPER + 1];     // shared temp counters (sequential builds)
__device__ int g_bsums[1024];         // scan partials

// ---------------------------------------------------------------------------
// f32x2 packed-FMA helpers (Blackwell; ptxas never emits FFMA2 from C++)
// ---------------------------------------------------------------------------
__device__ __forceinline__ u64 fma2(u64 a, u64 b, u64 c) {
    u64 d;
    asm("fma.rn.f32x2 %0, %1, %2, %3;" : "=l"(d) : "l"(a), "l"(b), "l"(c));
    return d;
}
__device__ __forceinline__ u64 dup2(float w) {
    u64 d;
    asm("mov.b64 %0, {%1, %1};" : "=l"(d) : "f"(w));
    return d;
}
__device__ __forceinline__ float lo32(u64 v) { return __uint_as_float((unsigned)v); }
__device__ __forceinline__ float hi32(u64 v) { return __uint_as_float((unsigned)(v >> 32)); }

// ---------------------------------------------------------------------------
// CSR build kernels
// ---------------------------------------------------------------------------
__global__ void zero_int_kernel(int* __restrict__ p, int n) {
    int stride = gridDim.x * blockDim.x;
    for (int i = blockIdx.x * blockDim.x + threadIdx.x; i < n; i += stride)
        p[i] = 0;
}

__global__ void hist_kernel(const int* __restrict__ dst, int* __restrict__ cnt, int n) {
    int i = blockIdx.x * blockDim.x + threadIdx.x;
    if (i < n) atomicAdd(&cnt[dst[i]], 1);
}

// Exclusive block-scan of 1024 elements; writes block total to bsums.
__global__ void scan_block_kernel(const int* __restrict__ in, int* __restrict__ out,
                                  int* __restrict__ bsums, int n) {
    __shared__ int sh[1024];
    int gid = blockIdx.x * 1024 + threadIdx.x;
    int v = (gid < n) ? in[gid] : 0;
    sh[threadIdx.x] = v;
    __syncthreads();
    for (int off = 1; off < 1024; off <<= 1) {
        int t = (threadIdx.x >= off) ? sh[threadIdx.x - off] : 0;
        __syncthreads();
        sh[threadIdx.x] += t;
        __syncthreads();
    }
    if (gid < n) out[gid] = sh[threadIdx.x] - v;   // exclusive
    if (threadIdx.x == 1023) bsums[blockIdx.x] = sh[1023];
}

// Single block: exclusive scan of block partials in place (nb <= 1024).
__global__ void scan_partials_kernel(int* __restrict__ bsums, int nb) {
    __shared__ int sh[1024];
    int v = (threadIdx.x < nb) ? bsums[threadIdx.x] : 0;
    sh[threadIdx.x] = v;
    __syncthreads();
    for (int off = 1; off < 1024; off <<= 1) {
        int t = (threadIdx.x >= off) ? sh[threadIdx.x - off] : 0;
        __syncthreads();
        sh[threadIdx.x] += t;
        __syncthreads();
    }
    if (threadIdx.x < nb) bsums[threadIdx.x] = sh[threadIdx.x] - v;
}

// Add block offsets; copy result to cnt (fill cursors); set rowptr[n] = E.
__global__ void scan_add_kernel(int* __restrict__ rowptr, int* __restrict__ cnt,
                                const int* __restrict__ bsums, int n, int E) {
    int gid = blockIdx.x * 1024 + threadIdx.x;
    if (gid < n) {
        int r = rowptr[gid] + bsums[blockIdx.x];
        rowptr[gid] = r;
        cnt[gid] = r;
    }
    if (gid == 0) rowptr[n] = E;
}

__global__ void fill_csr_kernel(const int* __restrict__ src, const int* __restrict__ dst,
                                int* __restrict__ cnt, int* __restrict__ col, int n) {
    int i = blockIdx.x * blockDim.x + threadIdx.x;
    if (i < n) {
        int p = atomicAdd(&cnt[dst[i]], 1);
        col[p] = src[i];
    }
}

// ---------------------------------------------------------------------------
// CSR gather-mean: warp per dst node.  Accumulate neighbor rows in registers,
// fold 1/deg, single clean store.  No atomics, no pre-zeroing.
// ---------------------------------------------------------------------------
__global__ void gather_mean_kernel(const float4* __restrict__ feat,
                                   const int* __restrict__ rowptr,
                                   const int* __restrict__ col,
                                   float4* __restrict__ out, int ndst) {
    int w = (blockIdx.x * blockDim.x + threadIdx.x) >> 5;
    int lane = threadIdx.x & 31;
    if (w >= ndst) return;
    int e0 = __ldg(&rowptr[w]);
    int e1 = __ldg(&rowptr[w + 1]);
    float4 acc = make_float4(0.f, 0.f, 0.f, 0.f);
    int e = e0;
    for (; e + 1 < e1; e += 2) {
        int s0 = __ldg(&col[e]);
        int s1 = __ldg(&col[e + 1]);
        float4 v0 = feat[(size_t)s0 * 32 + lane];
        float4 v1 = feat[(size_t)s1 * 32 + lane];
        acc.x += v0.x + v1.x; acc.y += v0.y + v1.y;
        acc.z += v0.z + v1.z; acc.w += v0.w + v1.w;
    }
    if (e < e1) {
        int s = __ldg(&col[e]);
        float4 v = feat[(size_t)s * 32 + lane];
        acc.x += v.x; acc.y += v.y; acc.z += v.z; acc.w += v.w;
    }
    float inv = 1.0f / fmaxf((float)(e1 - e0), 1.0f);
    acc.x *= inv; acc.y *= inv; acc.z *= inv; acc.w *= inv;
    out[(size_t)w * 32 + lane] = acc;
}

// ---------------------------------------------------------------------------
// ws[l] = Wr[l,0] + Wr[l,2]
// ---------------------------------------------------------------------------
__global__ void wsum_kernel(const float* __restrict__ Wr, float* __restrict__ ws) {
    int i = blockIdx.x * blockDim.x + threadIdx.x;
    const int T = 2 * HD * HD;
    if (i < T) {
        int l = i / (HD * HD);
        int o = i - l * (HD * HD);
        ws[i] = Wr[(l * 3 + 0) * HD * HD + o] + Wr[(l * 3 + 2) * HD * HD + o];
    }
}

// ---------------------------------------------------------------------------
// f32x2 SIMT GEMM, N = 128.  CTA = 256 threads, tile 64 rows x 128 cols.
// ---------------------------------------------------------------------------
__global__ __launch_bounds__(256)
void gemm_n128(const float* __restrict__ A, int M, int K,
               const float* __restrict__ W, const float* __restrict__ bias,
               float* __restrict__ Y, int relu) {
    __shared__ float AsT[16][68];
    __shared__ float Ws[16][128];
    int tid = threadIdx.x;
    int tx = tid & 31;
    int ty = tid >> 5;
    int rowBase = blockIdx.x * 64;
    u64 acc[4][4] = {};

    int rL = tid >> 2, q = tid & 3;
    int rowL = rowBase + rL; if (rowL > M - 1) rowL = M - 1;

    for (int k0 = 0; k0 < K; k0 += 16) {
        float4 av = *(const float4*)(A + (size_t)rowL * K + k0 + q * 4);
        AsT[q * 4 + 0][rL] = av.x;
        AsT[q * 4 + 1][rL] = av.y;
        AsT[q * 4 + 2][rL] = av.z;
        AsT[q * 4 + 3][rL] = av.w;
#pragma unroll
        for (int j = 0; j < 2; j++) {
            int i = tid + j * 256;
            int k = i >> 5, c = i & 31;
            *(float4*)&Ws[k][c * 4] =
                *(const float4*)(W + (size_t)(k0 + k) * 128 + c * 4);
        }
        __syncthreads();
#pragma unroll
        for (int k = 0; k < 16; k++) {
            ulonglong2 a01 = *(const ulonglong2*)&AsT[k][ty * 8];
            ulonglong2 a23 = *(const ulonglong2*)&AsT[k][ty * 8 + 4];
            float4 wv = *(float4*)&Ws[k][tx * 4];
            u64 w0 = dup2(wv.x), w1 = dup2(wv.y), w2 = dup2(wv.z), w3 = dup2(wv.w);
            acc[0][0] = fma2(a01.x, w0, acc[0][0]);
            acc[0][1] = fma2(a01.x, w1, acc[0][1]);
            acc[0][2] = fma2(a01.x, w2, acc[0][2]);
            acc[0][3] = fma2(a01.x, w3, acc[0][3]);
            acc[1][0] = fma2(a01.y, w0, acc[1][0]);
            acc[1][1] = fma2(a01.y, w1, acc[1][1]);
            acc[1][2] = fma2(a01.y, w2, acc[1][2]);
            acc[1][3] = fma2(a01.y, w3, acc[1][3]);
            acc[2][0] = fma2(a23.x, w0, acc[2][0]);
            acc[2][1] = fma2(a23.x, w1, acc[2][1]);
            acc[2][2] = fma2(a23.x, w2, acc[2][2]);
            acc[2][3] = fma2(a23.x, w3, acc[2][3]);
            acc[3][0] = fma2(a23.y, w0, acc[3][0]);
            acc[3][1] = fma2(a23.y, w1, acc[3][1]);
            acc[3][2] = fma2(a23.y, w2, acc[3][2]);
            acc[3][3] = fma2(a23.y, w3, acc[3][3]);
        }
        __syncthreads();
    }

    float4 bv = *(const float4*)(bias + tx * 4);
#pragma unroll
    for (int p = 0; p < 4; p++) {
#pragma unroll
        for (int h = 0; h < 2; h++) {
            int row = rowBase + ty * 8 + p * 2 + h;
            if (row < M) {
                float4 o;
                o.x = (h ? hi32(acc[p][0]) : lo32(acc[p][0])) + bv.x;
                o.y = (h ? hi32(acc[p][1]) : lo32(acc[p][1])) + bv.y;
                o.z = (h ? hi32(acc[p][2]) : lo32(acc[p][2])) + bv.z;
                o.w = (h ? hi32(acc[p][3]) : lo32(acc[p][3])) + bv.w;
                if (relu) {
                    o.x = fmaxf(o.x, 0.f); o.y = fmaxf(o.y, 0.f);
                    o.z = fmaxf(o.z, 0.f); o.w = fmaxf(o.w, 0.f);
                }
                *(float4*)(Y + (size_t)row * 128 + tx * 4) = o;
            }
        }
    }
}

// ---------------------------------------------------------------------------
// Fused multi-input f32x2 GEMM: Y = sum_s A_s @ W_s + b0 (+ b1).  K = 128.
// (means are pre-divided in the gather, so no per-row scales needed)
// ---------------------------------------------------------------------------
__global__ __launch_bounds__(256)
void gemm_multi128(const float* __restrict__ A0, const float* __restrict__ W0,
                   const float* __restrict__ A1, const float* __restrict__ W1,
                   const float* __restrict__ A2, const float* __restrict__ W2,
                   int nIn, int M,
                   const float* __restrict__ b0, const float* __restrict__ b1,
                   float* __restrict__ Y) {
    const float* Aar[3] = {A0, A1, A2};
    const float* War[3] = {W0, W1, W2};
    __shared__ float AsT[16][68];
    __shared__ float Ws[16][128];
    int tid = threadIdx.x;
    int tx = tid & 31;
    int ty = tid >> 5;
    int rowBase = blockIdx.x * 64;
    u64 acc[4][4] = {};

    int rL = tid >> 2, q = tid & 3;
    int rowL = rowBase + rL; if (rowL > M - 1) rowL = M - 1;

    for (int s = 0; s < nIn; s++) {
        const float* A = Aar[s];
        const float* W = War[s];
        for (int k0 = 0; k0 < 128; k0 += 16) {
            float4 av = *(const float4*)(A + (size_t)rowL * 128 + k0 + q * 4);
            AsT[q * 4 + 0][rL] = av.x;
            AsT[q * 4 + 1][rL] = av.y;
            AsT[q * 4 + 2][rL] = av.z;
            AsT[q * 4 + 3][rL] = av.w;
#pragma unroll
            for (int j = 0; j < 2; j++) {
                int i = tid + j * 256;
                int k = i >> 5, c = i & 31;
                *(float4*)&Ws[k][c * 4] =
                    *(const float4*)(W + (size_t)(k0 + k) * 128 + c * 4);
            }
            __syncthreads();
#pragma unroll
            for (int k = 0; k < 16; k++) {
                ulonglong2 a01 = *(const ulonglong2*)&AsT[k][ty * 8];
                ulonglong2 a23 = *(const ulonglong2*)&AsT[k][ty * 8 + 4];
                float4 wv = *(float4*)&Ws[k][tx * 4];
                u64 w0 = dup2(wv.x), w1 = dup2(wv.y), w2 = dup2(wv.z), w3 = dup2(wv.w);
                acc[0][0] = fma2(a01.x, w0, acc[0][0]);
                acc[0][1] = fma2(a01.x, w1, acc[0][1]);
                acc[0][2] = fma2(a01.x, w2, acc[0][2]);
                acc[0][3] = fma2(a01.x, w3, acc[0][3]);
                acc[1][0] = fma2(a01.y, w0, acc[1][0]);
                acc[1][1] = fma2(a01.y, w1, acc[1][1]);
                acc[1][2] = fma2(a01.y, w2, acc[1][2]);
                acc[1][3] = fma2(a01.y, w3, acc[1][3]);
                acc[2][0] = fma2(a23.x, w0, acc[2][0]);
                acc[2][1] = fma2(a23.x, w1, acc[2][1]);
                acc[2][2] = fma2(a23.x, w2, acc[2][2]);
                acc[2][3] = fma2(a23.x, w3, acc[2][3]);
                acc[3][0] = fma2(a23.y, w0, acc[3][0]);
                acc[3][1] = fma2(a23.y, w1, acc[3][1]);
                acc[3][2] = fma2(a23.y, w2, acc[3][2]);
                acc[3][3] = fma2(a23.y, w3, acc[3][3]);
            }
            __syncthreads();
        }
    }

    float4 bv = *(const float4*)(b0 + tx * 4);
    if (b1) {
        float4 b2 = *(const float4*)(b1 + tx * 4);
        bv.x += b2.x; bv.y += b2.y; bv.z += b2.z; bv.w += b2.w;
    }
#pragma unroll
    for (int p = 0; p < 4; p++) {
#pragma unroll
        for (int h = 0; h < 2; h++) {
            int row = rowBase + ty * 8 + p * 2 + h;
            if (row < M) {
                float4 o;
                o.x = (h ? hi32(acc[p][0]) : lo32(acc[p][0])) + bv.x;
                o.y = (h ? hi32(acc[p][1]) : lo32(acc[p][1])) + bv.y;
                o.z = (h ? hi32(acc[p][2]) : lo32(acc[p][2])) + bv.z;
                o.w = (h ? hi32(acc[p][3]) : lo32(acc[p][3])) + bv.w;
                *(float4*)(Y + (size_t)row * 128 + tx * 4) = o;
            }
        }
    }
}

// ---------------------------------------------------------------------------
// Final classifier GEMM (f32x2): [M,128] @ [128,64] + b.  Tile 64x64.
// ---------------------------------------------------------------------------
__global__ __launch_bounds__(256)
void gemm_n64(const float* __restrict__ A, int M,
              const float* __restrict__ W, const float* __restrict__ bias,
              float* __restrict__ Y) {
    __shared__ float AsT[16][68];
    __shared__ float Ws[16][64];
    int tid = threadIdx.x;
    int tx = tid & 15;
    int ty = tid >> 4;
    int rowBase = blockIdx.x * 64;
    u64 acc[2][4] = {};

    int rL = tid >> 2, q = tid & 3;
    int rowL = rowBase + rL; if (rowL > M - 1) rowL = M - 1;

    for (int k0 = 0; k0 < 128; k0 += 16) {
        float4 av = *(const float4*)(A + (size_t)rowL * 128 + k0 + q * 4);
        AsT[q * 4 + 0][rL] = av.x;
        AsT[q * 4 + 1][rL] = av.y;
        AsT[q * 4 + 2][rL] = av.z;
        AsT[q * 4 + 3][rL] = av.w;
        {
            int k = tid >> 4, c = tid & 15;
            *(float4*)&Ws[k][c * 4] =
                *(const float4*)(W + (size_t)(k0 + k) * 64 + c * 4);
        }
        __syncthreads();
#pragma unroll
        for (int k = 0; k < 16; k++) {
            ulonglong2 a01 = *(const ulonglong2*)&AsT[k][ty * 4];
            float4 wv = *(float4*)&Ws[k][tx * 4];
            u64 w0 = dup2(wv.x), w1 = dup2(wv.y), w2 = dup2(wv.z), w3 = dup2(wv.w);
            acc[0][0] = fma2(a01.x, w0, acc[0][0]);
            acc[0][1] = fma2(a01.x, w1, acc[0][1]);
            acc[0][2] = fma2(a01.x, w2, acc[0][2]);
            acc[0][3] = fma2(a01.x, w3, acc[0][3]);
            acc[1][0] = fma2(a01.y, w0, acc[1][0]);
            acc[1][1] = fma2(a01.y, w1, acc[1][1]);
            acc[1][2] = fma2(a01.y, w2, acc[1][2]);
            acc[1][3] = fma2(a01.y, w3, acc[1][3]);
        }
        __syncthreads();
    }

    float4 bv = *(const float4*)(bias + tx * 4);
#pragma unroll
    for (int p = 0; p < 2; p++) {
#pragma unroll
        for (int h = 0; h < 2; h++) {
            int row = rowBase + ty * 4 + p * 2 + h;
            if (row < M) {
                float4 o;
                o.x = (h ? hi32(acc[p][0]) : lo32(acc[p][0])) + bv.x;
                o.y = (h ? hi32(acc[p][1]) : lo32(acc[p][1])) + bv.y;
                o.z = (h ? hi32(acc[p][2]) : lo32(acc[p][2])) + bv.z;
                o.w = (h ? hi32(acc[p][3]) : lo32(acc[p][3])) + bv.w;
                *(float4*)(Y + (size_t)row * 64 + tx * 4) = o;
            }
        }
    }
}

// ---------------------------------------------------------------------------
// Host helper: build CSR for one edge type
// ---------------------------------------------------------------------------
static void build_csr(const int* src, const int* dst, int ndst,
                      int* rowptr, int* col, int* cnt, int* bsums) {
    int nb = (ndst + 1023) / 1024;
    zero_int_kernel<<<256, 256>>>(cnt, ndst);
    hist_kernel<<<(NEDGE + 255) / 256, 256>>>(dst, cnt, NEDGE);
    scan_block_kernel<<<nb, 1024>>>(cnt, rowptr, bsums, ndst);
    scan_partials_kernel<<<1, 1024>>>(bsums, nb);
    scan_add_kernel<<<nb, 1024>>>(rowptr, cnt, bsums, ndst, NEDGE);
    fill_csr_kernel<<<(NEDGE + 255) / 256, 256>>>(src, dst, cnt, col, NEDGE);
}

// ---------------------------------------------------------------------------
// Orchestration
// ---------------------------------------------------------------------------
extern "C" void kernel_launch(void* const* d_in, const int* in_sizes, int n_in,
                              void* d_out, int out_size) {
    const float* x_paper  = (const float*)d_in[0];
    const float* x_author = (const float*)d_in[1];
    const float* lin_p_w  = (const float*)d_in[2];
    const float* lin_p_b  = (const float*)d_in[3];
    const float* lin_a_w  = (const float*)d_in[4];
    const float* lin_a_b  = (const float*)d_in[5];
    const float* Wl       = (const float*)d_in[6];
    const float* bl       = (const float*)d_in[7];
    const float* Wr       = (const float*)d_in[8];
    const float* lin_w    = (const float*)d_in[9];
    const float* lin_b    = (const float*)d_in[10];
    const int* a2p_src = (const int*)d_in[11];
    const int* a2p_dst = (const int*)d_in[12];
    const int* p2a_src = (const int*)d_in[13];
    const int* p2a_dst = (const int*)d_in[14];
    const int* p2p_src = (const int*)d_in[15];
    const int* p2p_dst = (const int*)d_in[16];
    float* out = (float*)d_out;

    float *yp0, *yp1, *ya0, *ya1, *mp1, *mp2, *ma, *wsum;
    int *rp1, *rp2, *rp3, *c1, *c2, *c3, *cnt, *bsums;
    cudaGetSymbolAddress((void**)&yp0, g_yp0);
    cudaGetSymbolAddress((void**)&yp1, g_yp1);
    cudaGetSymbolAddress((void**)&ya0, g_ya0);
    cudaGetSymbolAddress((void**)&ya1, g_ya1);
    cudaGetSymbolAddress((void**)&mp1, g_mp1);
    cudaGetSymbolAddress((void**)&mp2, g_mp2);
    cudaGetSymbolAddress((void**)&ma,  g_ma);
    cudaGetSymbolAddress((void**)&wsum, g_wsum);
    cudaGetSymbolAddress((void**)&rp1, g_rp_a2p);
    cudaGetSymbolAddress((void**)&rp2, g_rp_p2a);
    cudaGetSymbolAddress((void**)&rp3, g_rp_p2p);
    cudaGetSymbolAddress((void**)&c1,  g_col_a2p);
    cudaGetSymbolAddress((void**)&c2,  g_col_p2a);
    cudaGetSymbolAddress((void**)&c3,  g_col_p2p);
    cudaGetSymbolAddress((void**)&cnt, g_cnt);
    cudaGetSymbolAddress((void**)&bsums, g_bsums);

    // --- CSR build (once; reused for both layers) ---
    build_csr(a2p_src, a2p_dst, NPAPER,  rp1, c1, cnt, bsums);
    build_csr(p2a_src, p2a_dst, NAUTHOR, rp2, c2, cnt, bsums);
    build_csr(p2p_src, p2p_dst, NPAPER,  rp3, c3, cnt, bsums);

    // --- Wr[l,0] + Wr[l,2] ---
    wsum_kernel<<<(2 * HD * HD + 255) / 256, 256>>>(Wr, wsum);

    // --- input projections + relu ---
    gemm_n128<<<(NPAPER + 63) / 64, 256>>>(x_paper, NPAPER, 256, lin_p_w, lin_p_b, yp0, 1);
    gemm_n128<<<(NAUTHOR + 63) / 64, 256>>>(x_author, NAUTHOR, 128, lin_a_w, lin_a_b, ya0, 1);

    float *ypc = yp0, *ypn = yp1, *yac = ya0, *yan = ya1;
    const int GP = (NPAPER * 32 + 255) / 256;   // warp per paper node
    const int GA = (NAUTHOR * 32 + 255) / 256;  // warp per author node

    for (int l = 0; l < 2; l++) {
        gather_mean_kernel<<<GP, 256>>>((const float4*)yac, rp1, c1, (float4*)mp1, NPAPER);
        gather_mean_kernel<<<GP, 256>>>((const float4*)ypc, rp3, c3, (float4*)mp2, NPAPER);
        gather_mean_kernel<<<GA, 256>>>((const float4*)ypc, rp2, c2, (float4*)ma,  NAUTHOR);

        // new_p = m_a2p@Wl[l,0] + m_p2p@Wl[l,2] + yp@(Wr[l,0]+Wr[l,2]) + bl[l,0]+bl[l,2]
        gemm_multi128<<<(NPAPER + 63) / 64, 256>>>(
            mp1, Wl + (size_t)(l * 3 + 0) * HD * HD,
            mp2, Wl + (size_t)(l * 3 + 2) * HD * HD,
            ypc, wsum + (size_t)l * HD * HD,
            3, NPAPER,
            bl + (size_t)(l * 3 + 0) * HD, bl + (size_t)(l * 3 + 2) * HD,
            ypn);

        // new_a = m_p2a@Wl[l,1] + ya@Wr[l,1] + bl[l,1]
        gemm_multi128<<<(NAUTHOR + 63) / 64, 256>>>(
            ma,  Wl + (size_t)(l * 3 + 1) * HD * HD,
            yac, Wr + (size_t)(l * 3 + 1) * HD * HD,
            nullptr, nullptr,
            2, NAUTHOR,
            bl + (size_t)(l * 3 + 1) * HD, nullptr,
            yan);

        float* t;
        t = ypc; ypc = ypn; ypn = t;
        t = yac; yac = yan; yan = t;
    }

    // --- final classifier on papers ---
    gemm_n64<<<(NPAPER + 63) / 64, 256>>>(ypc, NPAPER, lin_w, lin_b, out);
}

// round 7
// speedup vs baseline: 1.6315x; 1.0857x over previous
#include <cuda_runtime.h>
#include <cuda_bf16.h>
#include <cstdint>
#include <cstddef>

// ---------------------------------------------------------------------------
// Problem constants
// ---------------------------------------------------------------------------
#define NPAPER  100000
#define NAUTHOR 50000
#define NEDGE   600000
#define HD      128
#define IMG     16384          // elements per weight image (128x128)
#define ROWP    72             // padded row stride (bf16 elems) in smem tiles

// ---------------------------------------------------------------------------
// Static scratch
// ---------------------------------------------------------------------------
__device__ float g_yp0[(size_t)NPAPER * HD];
__device__ float g_yp1[(size_t)NPAPER * HD];
__device__ float g_ya0[(size_t)NAUTHOR * HD];
__device__ float g_ya1[(size_t)NAUTHOR * HD];
__device__ float g_mp1[(size_t)NPAPER * HD];
__device__ float g_mp2[(size_t)NPAPER * HD];
__device__ float g_ma [(size_t)NAUTHOR * HD];

__device__ int g_rp_a2p[NPAPER + 1];
__device__ int g_rp_p2a[NAUTHOR + 1];
__device__ int g_rp_p2p[NPAPER + 1];
__device__ int g_col_a2p[NEDGE];
__device__ int g_col_p2a[NEDGE];
__device__ int g_col_p2p[NEDGE];
__device__ int g_cnt[NPAPER + 1];
__device__ int g_bsums[1024];

// Pre-split bf16 weight images, transposed to [n][k] (14 images)
__device__ unsigned short g_wih[14 * IMG];
__device__ unsigned short g_wil[14 * IMG];

// ---------------------------------------------------------------------------
// bf16 split helpers
// ---------------------------------------------------------------------------
__device__ __forceinline__ void splitbf(float f, unsigned short& h, float& lo) {
    __nv_bfloat16 b = __float2bfloat16(f);
    h = __bfloat16_as_ushort(b);
    lo = f - __bfloat162float(b);
}
__device__ __forceinline__ unsigned short bf16of(float f) {
    __nv_bfloat16 b = __float2bfloat16(f);
    return __bfloat16_as_ushort(b);
}

// mma.sync m16n8k16 row.col f32.bf16.bf16.f32  (baseline sm_80+ PTX — no 'a' features)
__device__ __forceinline__ void mma16816(float* c, const uint32_t* a, const uint32_t* b) {
    asm volatile(
        "mma.sync.aligned.m16n8k16.row.col.f32.bf16.bf16.f32 "
        "{%0,%1,%2,%3}, {%4,%5,%6,%7}, {%8,%9}, {%0,%1,%2,%3};"
        : "+f"(c[0]), "+f"(c[1]), "+f"(c[2]), "+f"(c[3])
        : "r"(a[0]), "r"(a[1]), "r"(a[2]), "r"(a[3]), "r"(b[0]), "r"(b[1]));
}

// ---------------------------------------------------------------------------
// Weight prep: split W into bf16 hi/lo, transposed to [n][k].
// ---------------------------------------------------------------------------
__global__ void prep_w_kernel(const float* __restrict__ lin_p_w, const float* __restrict__ lin_a_w,
                              const float* __restrict__ Wl, const float* __restrict__ Wr,
                              const float* __restrict__ lin_w,
                              unsigned short* __restrict__ ih, unsigned short* __restrict__ il) {
    int img = blockIdx.x;
    int N = (img == 13) ? 64 : 128;
    int total = N * 128;
    for (int i = threadIdx.x; i < total; i += blockDim.x) {
        int n = i / 128, k = i % 128;
        float w;
        if (img == 0)       w = lin_p_w[k * 128 + n];
        else if (img == 1)  w = lin_p_w[(k + 128) * 128 + n];
        else if (img == 2)  w = lin_a_w[k * 128 + n];
        else if (img <= 8)  w = Wl[(size_t)(img - 3) * IMG + k * 128 + n];
        else if (img <= 10) {
            int l = img - 9;
            w = Wr[(size_t)(l * 3 + 0) * IMG + k * 128 + n] +
                Wr[(size_t)(l * 3 + 2) * IMG + k * 128 + n];
        }
        else if (img <= 12) w = Wr[(size_t)((img - 11) * 3 + 1) * IMG + k * 128 + n];
        else                w = lin_w[k * 64 + n];
        unsigned short h; float lo;
        splitbf(w, h, lo);
        size_t base = (size_t)img * IMG + (size_t)n * 128 + k;
        ih[base] = h;
        il[base] = bf16of(lo);
    }
}

// ---------------------------------------------------------------------------
// Split-bf16 tensor-core GEMM via mma.sync.  CTA = 256 threads, tile 128 x N.
// 8 warps (4 m x 2 n), warp tile 32 x N/2.  K staged in 64-chunks:
// A (f32) split to bf16 hi/lo in smem; W hi/lo copied from prepped images.
// Y = sum_stages A_s @ W_s + b0 (+ b1), optional relu.
// ---------------------------------------------------------------------------
#define SA_HI 0
#define SA_LO (128 * ROWP * 2)
#define SW_HI (2 * 128 * ROWP * 2)
#define SW_LO (3 * 128 * ROWP * 2)
#define SMEM_TOTAL (4 * 128 * ROWP * 2)   // 73728 B

template<int N>
__global__ void __launch_bounds__(256, 2)
gemm_mma(const float* A0, int lda0, int ko0, const unsigned short* Wh0, const unsigned short* Wl0,
         const float* A1, int lda1, int ko1, const unsigned short* Wh1, const unsigned short* Wl1,
         const float* A2, int lda2, int ko2, const unsigned short* Wh2, const unsigned short* Wl2,
         int nStages, int M, const float* b0, const float* b1, float* Y, int relu) {
    extern __shared__ char smem[];
    const int NT = N / 16;                 // n-tiles per warp
    int tid = threadIdx.x, wid = tid >> 5, lane = tid & 31;
    int g = lane >> 2, t4 = lane & 3;      // mma fragment coords
    int warp_m = wid & 3, warp_n = wid >> 2;
    int rowBase = blockIdx.x * 128;

    const float* As[3] = {A0, A1, A2};
    const int ldas[3] = {lda0, lda1, lda2};
    const int kos[3] = {ko0, ko1, ko2};
    const unsigned short* Whs[3] = {Wh0, Wh1, Wh2};
    const unsigned short* Wls[3] = {Wl0, Wl1, Wl2};

    float c[2][8][4];                      // [mtile][ntile][frag] (NT <= 8)
#pragma unroll
    for (int m = 0; m < 2; m++)
#pragma unroll
        for (int n = 0; n < 8; n++)
#pragma unroll
            for (int q = 0; q < 4; q++) c[m][n][q] = 0.f;

    // A staging geometry: thread handles row = tid>>1, k half = (tid&1)*32
    int sr = tid >> 1;
    int skh = (tid & 1) << 5;

    for (int s = 0; s < nStages; s++) {
        const float* Abase = As[s];
        int lda = ldas[s], ko = kos[s];
        const unsigned short* wh = Whs[s];
        const unsigned short* wl = Wls[s];
        for (int kc = 0; kc < 128; kc += 64) {
            // --- stage W hi/lo: [n][64] slice, padded rows ---
            for (int i = tid; i < N * 8; i += 256) {
                int n = i >> 3, j = i & 7;
                const unsigned short* ph = wh + (size_t)n * 128 + kc + j * 8;
                const unsigned short* pl = wl + (size_t)n * 128 + kc + j * 8;
                *(uint4*)(smem + SW_HI + (n * ROWP + j * 8) * 2) = *(const uint4*)ph;
                *(uint4*)(smem + SW_LO + (n * ROWP + j * 8) * 2) = *(const uint4*)pl;
            }
            // --- stage A: load f32, split, store bf16 hi/lo ---
            {
                int grow = rowBase + sr; if (grow > M - 1) grow = M - 1;
                const float* arow = Abase + (size_t)grow * lda + ko + kc + skh;
#pragma unroll
                for (int q = 0; q < 4; q++) {
                    float4 fa = *(const float4*)(arow + q * 8);
                    float4 fb = *(const float4*)(arow + q * 8 + 4);
                    unsigned short h[8]; float lo[8];
                    splitbf(fa.x, h[0], lo[0]); splitbf(fa.y, h[1], lo[1]);
                    splitbf(fa.z, h[2], lo[2]); splitbf(fa.w, h[3], lo[3]);
                    splitbf(fb.x, h[4], lo[4]); splitbf(fb.y, h[5], lo[5]);
                    splitbf(fb.z, h[6], lo[6]); splitbf(fb.w, h[7], lo[7]);
                    uint4 hv, lv;
                    hv.x = (uint32_t)h[0] | ((uint32_t)h[1] << 16);
                    hv.y = (uint32_t)h[2] | ((uint32_t)h[3] << 16);
                    hv.z = (uint32_t)h[4] | ((uint32_t)h[5] << 16);
                    hv.w = (uint32_t)h[6] | ((uint32_t)h[7] << 16);
                    lv.x = (uint32_t)bf16of(lo[0]) | ((uint32_t)bf16of(lo[1]) << 16);
                    lv.y = (uint32_t)bf16of(lo[2]) | ((uint32_t)bf16of(lo[3]) << 16);
                    lv.z = (uint32_t)bf16of(lo[4]) | ((uint32_t)bf16of(lo[5]) << 16);
                    lv.w = (uint32_t)bf16of(lo[6]) | ((uint32_t)bf16of(lo[7]) << 16);
                    uint32_t off = (sr * ROWP + skh + q * 8) * 2;
                    *(uint4*)(smem + SA_HI + off) = hv;
                    *(uint4*)(smem + SA_LO + off) = lv;
                }
            }
            __syncthreads();

            // --- mma over 4 k16 steps ---
#pragma unroll
            for (int k16 = 0; k16 < 64; k16 += 16) {
                uint32_t ah[2][4], al[2][4];
#pragma unroll
                for (int mt = 0; mt < 2; mt++) {
                    int row = warp_m * 32 + mt * 16 + g;
                    uint32_t o00 = (row * ROWP + k16 + t4 * 2) * 2;
                    uint32_t o10 = ((row + 8) * ROWP + k16 + t4 * 2) * 2;
                    ah[mt][0] = *(const uint32_t*)(smem + SA_HI + o00);
                    ah[mt][1] = *(const uint32_t*)(smem + SA_HI + o10);
                    ah[mt][2] = *(const uint32_t*)(smem + SA_HI + o00 + 16);
                    ah[mt][3] = *(const uint32_t*)(smem + SA_HI + o10 + 16);
                    al[mt][0] = *(const uint32_t*)(smem + SA_LO + o00);
                    al[mt][1] = *(const uint32_t*)(smem + SA_LO + o10);
                    al[mt][2] = *(const uint32_t*)(smem + SA_LO + o00 + 16);
                    al[mt][3] = *(const uint32_t*)(smem + SA_LO + o10 + 16);
                }
#pragma unroll
                for (int nt = 0; nt < NT; nt++) {
                    int n = warp_n * (N / 2) + nt * 8 + g;
                    uint32_t ob = (n * ROWP + k16 + t4 * 2) * 2;
                    uint32_t bh[2], blo[2];
                    bh[0]  = *(const uint32_t*)(smem + SW_HI + ob);
                    bh[1]  = *(const uint32_t*)(smem + SW_HI + ob + 16);
                    blo[0] = *(const uint32_t*)(smem + SW_LO + ob);
                    blo[1] = *(const uint32_t*)(smem + SW_LO + ob + 16);
#pragma unroll
                    for (int mt = 0; mt < 2; mt++) {
                        mma16816(c[mt][nt], ah[mt], bh);
                        mma16816(c[mt][nt], ah[mt], blo);
                        mma16816(c[mt][nt], al[mt], bh);
                    }
                }
            }
            __syncthreads();
        }
    }

    // --- epilogue ---
#pragma unroll
    for (int mt = 0; mt < 2; mt++) {
        int r0 = rowBase + warp_m * 32 + mt * 16 + g;
        int r1 = r0 + 8;
#pragma unroll
        for (int nt = 0; nt < NT; nt++) {
            int col = warp_n * (N / 2) + nt * 8 + t4 * 2;
            float bx = b0[col], by = b0[col + 1];
            if (b1) { bx += b1[col]; by += b1[col + 1]; }
            float2 o0, o1;
            o0.x = c[mt][nt][0] + bx; o0.y = c[mt][nt][1] + by;
            o1.x = c[mt][nt][2] + bx; o1.y = c[mt][nt][3] + by;
            if (relu) {
                o0.x = fmaxf(o0.x, 0.f); o0.y = fmaxf(o0.y, 0.f);
                o1.x = fmaxf(o1.x, 0.f); o1.y = fmaxf(o1.y, 0.f);
            }
            if (r0 < M) *(float2*)(Y + (size_t)r0 * N + col) = o0;
            if (r1 < M) *(float2*)(Y + (size_t)r1 * N + col) = o1;
        }
    }
}

// ---------------------------------------------------------------------------
// CSR build kernels (proven R5 code)
// ---------------------------------------------------------------------------
__global__ void zero_int_kernel(int* __restrict__ p, int n) {
    int stride = gridDim.x * blockDim.x;
    for (int i = blockIdx.x * blockDim.x + threadIdx.x; i < n; i += stride) p[i] = 0;
}
__global__ void hist_kernel(const int* __restrict__ dst, int* __restrict__ cnt, int n) {
    int i = blockIdx.x * blockDim.x + threadIdx.x;
    if (i < n) atomicAdd(&cnt[dst[i]], 1);
}
__global__ void scan_block_kernel(const int* __restrict__ in, int* __restrict__ out,
                                  int* __restrict__ bsums, int n) {
    __shared__ int sh[1024];
    int gid = blockIdx.x * 1024 + threadIdx.x;
    int v = (gid < n) ? in[gid] : 0;
    sh[threadIdx.x] = v;
    __syncthreads();
    for (int off = 1; off < 1024; off <<= 1) {
        int t = (threadIdx.x >= off) ? sh[threadIdx.x - off] : 0;
        __syncthreads();
        sh[threadIdx.x] += t;
        __syncthreads();
    }
    if (gid < n) out[gid] = sh[threadIdx.x] - v;
    if (threadIdx.x == 1023) bsums[blockIdx.x] = sh[1023];
}
__global__ void scan_partials_kernel(int* __restrict__ bsums, int nb) {
    __shared__ int sh[1024];
    int v = (threadIdx.x < nb) ? bsums[threadIdx.x] : 0;
    sh[threadIdx.x] = v;
    __syncthreads();
    for (int off = 1; off < 1024; off <<= 1) {
        int t = (threadIdx.x >= off) ? sh[threadIdx.x - off] : 0;
        __syncthreads();
        sh[threadIdx.x] += t;
        __syncthreads();
    }
    if (threadIdx.x < nb) bsums[threadIdx.x] = sh[threadIdx.x] - v;
}
__global__ void scan_add_kernel(int* __restrict__ rowptr, int* __restrict__ cnt,
                                const int* __restrict__ bsums, int n, int E) {
    int gid = blockIdx.x * 1024 + threadIdx.x;
    if (gid < n) {
        int r = rowptr[gid] + bsums[blockIdx.x];
        rowptr[gid] = r;
        cnt[gid] = r;
    }
    if (gid == 0) rowptr[n] = E;
}
__global__ void fill_csr_kernel(const int* __restrict__ src, const int* __restrict__ dst,
                                int* __restrict__ cnt, int* __restrict__ col, int n) {
    int i = blockIdx.x * blockDim.x + threadIdx.x;
    if (i < n) {
        int p = atomicAdd(&cnt[dst[i]], 1);
        col[p] = src[i];
    }
}

// ---------------------------------------------------------------------------
// Fused 3-way gather-mean (proven R6 component — same as R5 math)
// ---------------------------------------------------------------------------
__device__ __forceinline__ void gather_one(const float4* __restrict__ feat,
                                           const int* __restrict__ rowptr,
                                           const int* __restrict__ col,
                                           float4* __restrict__ out, int node, int lane) {
    int e0 = __ldg(&rowptr[node]);
    int e1 = __ldg(&rowptr[node + 1]);
    float4 a0 = make_float4(0.f, 0.f, 0.f, 0.f);
    float4 a1 = make_float4(0.f, 0.f, 0.f, 0.f);
    int e = e0;
    for (; e + 3 < e1; e += 4) {
        int s0 = __ldg(&col[e]);
        int s1 = __ldg(&col[e + 1]);
        int s2 = __ldg(&col[e + 2]);
        int s3 = __ldg(&col[e + 3]);
        float4 v0 = feat[(size_t)s0 * 32 + lane];
        float4 v1 = feat[(size_t)s1 * 32 + lane];
        float4 v2 = feat[(size_t)s2 * 32 + lane];
        float4 v3 = feat[(size_t)s3 * 32 + lane];
        a0.x += v0.x + v1.x; a0.y += v0.y + v1.y; a0.z += v0.z + v1.z; a0.w += v0.w + v1.w;
        a1.x += v2.x + v3.x; a1.y += v2.y + v3.y; a1.z += v2.z + v3.z; a1.w += v2.w + v3.w;
    }
    for (; e < e1; e++) {
        int s = __ldg(&col[e]);
        float4 v = feat[(size_t)s * 32 + lane];
        a0.x += v.x; a0.y += v.y; a0.z += v.z; a0.w += v.w;
    }
    float inv = 1.0f / fmaxf((float)(e1 - e0), 1.0f);
    float4 o;
    o.x = (a0.x + a1.x) * inv; o.y = (a0.y + a1.y) * inv;
    o.z = (a0.z + a1.z) * inv; o.w = (a0.w + a1.w) * inv;
    out[(size_t)node * 32 + lane] = o;
}

__global__ void gather3_kernel(const float4* __restrict__ featA, const float4* __restrict__ featP,
                               const int* __restrict__ rp1, const int* __restrict__ c1, float4* __restrict__ mp1,
                               const int* __restrict__ rp3, const int* __restrict__ c3, float4* __restrict__ mp2,
                               const int* __restrict__ rp2, const int* __restrict__ c2, float4* __restrict__ ma) {
    int w = (blockIdx.x * blockDim.x + threadIdx.x) >> 5;
    int lane = threadIdx.x & 31;
    if (w < NPAPER) {
        gather_one(featA, rp1, c1, mp1, w, lane);
    } else if (w < 2 * NPAPER) {
        gather_one(featP, rp3, c3, mp2, w - NPAPER, lane);
    } else if (w < 2 * NPAPER + NAUTHOR) {
        gather_one(featP, rp2, c2, ma, w - 2 * NPAPER, lane);
    }
}

// ---------------------------------------------------------------------------
// Host helpers
// ---------------------------------------------------------------------------
static void build_csr(const int* src, const int* dst, int ndst,
                      int* rowptr, int* col, int* cnt, int* bsums) {
    int nb = (ndst + 1023) / 1024;
    zero_int_kernel<<<256, 256>>>(cnt, ndst);
    hist_kernel<<<(NEDGE + 255) / 256, 256>>>(dst, cnt, NEDGE);
    scan_block_kernel<<<nb, 1024>>>(cnt, rowptr, bsums, ndst);
    scan_partials_kernel<<<1, 1024>>>(bsums, nb);
    scan_add_kernel<<<nb, 1024>>>(rowptr, cnt, bsums, ndst, NEDGE);
    fill_csr_kernel<<<(NEDGE + 255) / 256, 256>>>(src, dst, cnt, col, NEDGE);
}

extern "C" void kernel_launch(void* const* d_in, const int* in_sizes, int n_in,
                              void* d_out, int out_size) {
    const float* x_paper  = (const float*)d_in[0];
    const float* x_author = (const float*)d_in[1];
    const float* lin_p_w  = (const float*)d_in[2];
    const float* lin_p_b  = (const float*)d_in[3];
    const float* lin_a_w  = (const float*)d_in[4];
    const float* lin_a_b  = (const float*)d_in[5];
    const float* Wl       = (const float*)d_in[6];
    const float* bl       = (const float*)d_in[7];
    const float* Wr       = (const float*)d_in[8];
    const float* lin_w    = (const float*)d_in[9];
    const float* lin_b    = (const float*)d_in[10];
    const int* a2p_src = (const int*)d_in[11];
    const int* a2p_dst = (const int*)d_in[12];
    const int* p2a_src = (const int*)d_in[13];
    const int* p2a_dst = (const int*)d_in[14];
    const int* p2p_src = (const int*)d_in[15];
    const int* p2p_dst = (const int*)d_in[16];
    float* out = (float*)d_out;

    float *yp0, *yp1, *ya0, *ya1, *mp1, *mp2, *ma;
    int *rp1, *rp2, *rp3, *c1, *c2, *c3, *cnt, *bsums;
    unsigned short *wih, *wil;
    cudaGetSymbolAddress((void**)&yp0, g_yp0);
    cudaGetSymbolAddress((void**)&yp1, g_yp1);
    cudaGetSymbolAddress((void**)&ya0, g_ya0);
    cudaGetSymbolAddress((void**)&ya1, g_ya1);
    cudaGetSymbolAddress((void**)&mp1, g_mp1);
    cudaGetSymbolAddress((void**)&mp2, g_mp2);
    cudaGetSymbolAddress((void**)&ma,  g_ma);
    cudaGetSymbolAddress((void**)&rp1, g_rp_a2p);
    cudaGetSymbolAddress((void**)&rp2, g_rp_p2a);
    cudaGetSymbolAddress((void**)&rp3, g_rp_p2p);
    cudaGetSymbolAddress((void**)&c1,  g_col_a2p);
    cudaGetSymbolAddress((void**)&c2,  g_col_p2a);
    cudaGetSymbolAddress((void**)&c3,  g_col_p2p);
    cudaGetSymbolAddress((void**)&cnt, g_cnt);
    cudaGetSymbolAddress((void**)&bsums, g_bsums);
    cudaGetSymbolAddress((void**)&wih, g_wih);
    cudaGetSymbolAddress((void**)&wil, g_wil);

    cudaFuncSetAttribute(gemm_mma<128>, cudaFuncAttributeMaxDynamicSharedMemorySize, SMEM_TOTAL);
    cudaFuncSetAttribute(gemm_mma<64>,  cudaFuncAttributeMaxDynamicSharedMemorySize, SMEM_TOTAL);

    const int GP = (NPAPER + 127) / 128;
    const int GA = (NAUTHOR + 127) / 128;

    // 1: weight prep
    prep_w_kernel<<<14, 256>>>(lin_p_w, lin_a_w, Wl, Wr, lin_w, wih, wil);
    // 2: first CSR zero
    zero_int_kernel<<<256, 256>>>(cnt, NPAPER);
    // 3: paper projection (K=256 -> 2 stages), relu
    gemm_mma<128><<<GP, 256, SMEM_TOTAL>>>(
        x_paper, 256, 0,   wih + 0 * IMG, wil + 0 * IMG,
        x_paper, 256, 128, wih + 1 * IMG, wil + 1 * IMG,
        nullptr, 0, 0, nullptr, nullptr,
        2, NPAPER, lin_p_b, nullptr, yp0, 1);
    // 4: author projection (ncu capture slot), relu
    gemm_mma<128><<<GA, 256, SMEM_TOTAL>>>(
        x_author, 128, 0, wih + 2 * IMG, wil + 2 * IMG,
        nullptr, 0, 0, nullptr, nullptr,
        nullptr, 0, 0, nullptr, nullptr,
        1, NAUTHOR, lin_a_b, nullptr, ya0, 1);

    // finish CSR a2p (cnt already zeroed)
    {
        int nb = (NPAPER + 1023) / 1024;
        hist_kernel<<<(NEDGE + 255) / 256, 256>>>(a2p_dst, cnt, NEDGE);
        scan_block_kernel<<<nb, 1024>>>(cnt, rp1, bsums, NPAPER);
        scan_partials_kernel<<<1, 1024>>>(bsums, nb);
        scan_add_kernel<<<nb, 1024>>>(rp1, cnt, bsums, NPAPER, NEDGE);
        fill_csr_kernel<<<(NEDGE + 255) / 256, 256>>>(a2p_src, a2p_dst, cnt, c1, NEDGE);
    }
    build_csr(p2a_src, p2a_dst, NAUTHOR, rp2, c2, cnt, bsums);
    build_csr(p2p_src, p2p_dst, NPAPER,  rp3, c3, cnt, bsums);

    float *ypc = yp0, *ypn = yp1, *yac = ya0, *yan = ya1;
    const int GG = ((2 * NPAPER + NAUTHOR) * 32 + 255) / 256;

    for (int l = 0; l < 2; l++) {
        gather3_kernel<<<GG, 256>>>((const float4*)yac, (const float4*)ypc,
                                    rp1, c1, (float4*)mp1,
                                    rp3, c3, (float4*)mp2,
                                    rp2, c2, (float4*)ma);

        // new_p = m_a2p@Wl[l,0] + m_p2p@Wl[l,2] + yp@(Wr[l,0]+Wr[l,2]) + biases
        gemm_mma<128><<<GP, 256, SMEM_TOTAL>>>(
            mp1, 128, 0, wih + (3 + l * 3 + 0) * IMG, wil + (3 + l * 3 + 0) * IMG,
            mp2, 128, 0, wih + (3 + l * 3 + 2) * IMG, wil + (3 + l * 3 + 2) * IMG,
            ypc, 128, 0, wih + (9 + l) * IMG,          wil + (9 + l) * IMG,
            3, NPAPER,
            bl + (size_t)(l * 3 + 0) * HD, bl + (size_t)(l * 3 + 2) * HD, ypn, 0);

        // new_a = m_p2a@Wl[l,1] + ya@Wr[l,1] + bl[l,1]
        gemm_mma<128><<<GA, 256, SMEM_TOTAL>>>(
            ma,  128, 0, wih + (3 + l * 3 + 1) * IMG, wil + (3 + l * 3 + 1) * IMG,
            yac, 128, 0, wih + (11 + l) * IMG,         wil + (11 + l) * IMG,
            nullptr, 0, 0, nullptr, nullptr,
            2, NAUTHOR,
            bl + (size_t)(l * 3 + 1) * HD, nullptr, yan, 0);

        float* t;
        t = ypc; ypc = ypn; ypn = t;
        t = yac; yac = yan; yan = t;
    }

    // final classifier (N=64)
    gemm_mma<64><<<GP, 256, SMEM_TOTAL>>>(
        ypc, 128, 0, wih + 13 * IMG, wil + 13 * IMG,
        nullptr, 0, 0, nullptr, nullptr,
        nullptr, 0, 0, nullptr, nullptr,
        1, NPAPER, lin_b, nullptr, out, 0);
}

// round 8
// speedup vs baseline: 1.7830x; 1.0929x over previous
#include <cuda_runtime.h>
#include <cuda_bf16.h>
#include <cstdint>
#include <cstddef>

// ---------------------------------------------------------------------------
// Problem constants
// ---------------------------------------------------------------------------
#define NPAPER  100000
#define NAUTHOR 50000
#define NEDGE   600000
#define HD      128
#define IMG     16384          // elements per weight image (128x128)
#define ROWP    72             // padded row stride (bf16 elems) in smem tiles

// ---------------------------------------------------------------------------
// Static scratch
// ---------------------------------------------------------------------------
__device__ float g_yp0[(size_t)NPAPER * HD];
__device__ float g_yp1[(size_t)NPAPER * HD];
__device__ float g_ya0[(size_t)NAUTHOR * HD];
__device__ float g_ya1[(size_t)NAUTHOR * HD];
__device__ float g_mp1[(size_t)NPAPER * HD];
__device__ float g_mp2[(size_t)NPAPER * HD];
__device__ float g_ma [(size_t)NAUTHOR * HD];

__device__ int g_rp_a2p[NPAPER + 1];
__device__ int g_rp_p2a[NAUTHOR + 1];
__device__ int g_rp_p2p[NPAPER + 1];
__device__ int g_col_a2p[NEDGE];
__device__ int g_col_p2a[NEDGE];
__device__ int g_col_p2p[NEDGE];
__device__ int g_cnt[NPAPER + 1];
__device__ int g_bsums[1024];

// Pre-split bf16 weight images, transposed to [n][k] (14 images)
__device__ unsigned short g_wih[14 * IMG];
__device__ unsigned short g_wil[14 * IMG];

// ---------------------------------------------------------------------------
// helpers
// ---------------------------------------------------------------------------
__device__ __forceinline__ uint32_t smem_u32(const void* p) {
    uint32_t a;
    asm("{ .reg .u64 t; cvta.to.shared.u64 t, %1; cvt.u32.u64 %0, t; }" : "=r"(a) : "l"(p));
    return a;
}
__device__ __forceinline__ void splitbf(float f, unsigned short& h, float& lo) {
    __nv_bfloat16 b = __float2bfloat16(f);
    h = __bfloat16_as_ushort(b);
    lo = f - __bfloat162float(b);
}
__device__ __forceinline__ unsigned short bf16of(float f) {
    __nv_bfloat16 b = __float2bfloat16(f);
    return __bfloat16_as_ushort(b);
}

// mma.sync m16n8k16 row.col f32.bf16.bf16.f32  (baseline sm_80+)
__device__ __forceinline__ void mma16816(float* c, const uint32_t* a, const uint32_t* b) {
    asm volatile(
        "mma.sync.aligned.m16n8k16.row.col.f32.bf16.bf16.f32 "
        "{%0,%1,%2,%3}, {%4,%5,%6,%7}, {%8,%9}, {%0,%1,%2,%3};"
        : "+f"(c[0]), "+f"(c[1]), "+f"(c[2]), "+f"(c[3])
        : "r"(a[0]), "r"(a[1]), "r"(a[2]), "r"(a[3]), "r"(b[0]), "r"(b[1]));
}
// ldmatrix x4 (baseline sm_75+)
__device__ __forceinline__ void ldm_x4(uint32_t* r, uint32_t addr) {
    asm volatile("ldmatrix.sync.aligned.m8n8.x4.shared.b16 {%0,%1,%2,%3}, [%4];"
                 : "=r"(r[0]), "=r"(r[1]), "=r"(r[2]), "=r"(r[3]) : "r"(addr));
}

// ---------------------------------------------------------------------------
// Weight prep: split W into bf16 hi/lo, transposed to [n][k].
// ---------------------------------------------------------------------------
__global__ void prep_w_kernel(const float* __restrict__ lin_p_w, const float* __restrict__ lin_a_w,
                              const float* __restrict__ Wl, const float* __restrict__ Wr,
                              const float* __restrict__ lin_w,
                              unsigned short* __restrict__ ih, unsigned short* __restrict__ il) {
    int img = blockIdx.x;
    int N = (img == 13) ? 64 : 128;
    int total = N * 128;
    for (int i = threadIdx.x; i < total; i += blockDim.x) {
        int n = i / 128, k = i % 128;
        float w;
        if (img == 0)       w = lin_p_w[k * 128 + n];
        else if (img == 1)  w = lin_p_w[(k + 128) * 128 + n];
        else if (img == 2)  w = lin_a_w[k * 128 + n];
        else if (img <= 8)  w = Wl[(size_t)(img - 3) * IMG + k * 128 + n];
        else if (img <= 10) {
            int l = img - 9;
            w = Wr[(size_t)(l * 3 + 0) * IMG + k * 128 + n] +
                Wr[(size_t)(l * 3 + 2) * IMG + k * 128 + n];
        }
        else if (img <= 12) w = Wr[(size_t)((img - 11) * 3 + 1) * IMG + k * 128 + n];
        else                w = lin_w[k * 64 + n];
        unsigned short h; float lo;
        splitbf(w, h, lo);
        size_t base = (size_t)img * IMG + (size_t)n * 128 + k;
        ih[base] = h;
        il[base] = bf16of(lo);
    }
}

// ---------------------------------------------------------------------------
// Split-bf16 tensor-core GEMM via mma.sync + ldmatrix.  CTA = 256 threads,
// tile 128 x N.  8 warps (4 m x 2 n), warp tile 32 x N/2.
// ---------------------------------------------------------------------------
#define SA_HI 0
#define SA_LO (128 * ROWP * 2)
#define SW_HI (2 * 128 * ROWP * 2)
#define SW_LO (3 * 128 * ROWP * 2)
#define SMEM_TOTAL (4 * 128 * ROWP * 2)   // 73728 B

template<int N>
__global__ void __launch_bounds__(256, 2)
gemm_mma(const float* A0, int lda0, int ko0, const unsigned short* Wh0, const unsigned short* Wl0,
         const float* A1, int lda1, int ko1, const unsigned short* Wh1, const unsigned short* Wl1,
         const float* A2, int lda2, int ko2, const unsigned short* Wh2, const unsigned short* Wl2,
         int nStages, int M, const float* b0, const float* b1, float* Y, int relu) {
    extern __shared__ char smem[];
    const int NT = N / 16;                 // n-tiles per warp
    int tid = threadIdx.x, wid = tid >> 5, lane = tid & 31;
    int g = lane >> 2, t4 = lane & 3;
    int warp_m = wid & 3, warp_n = wid >> 2;
    int rowBase = blockIdx.x * 128;
    uint32_t sb = smem_u32(smem);

    const float* As[3] = {A0, A1, A2};
    const int ldas[3] = {lda0, lda1, lda2};
    const int kos[3] = {ko0, ko1, ko2};
    const unsigned short* Whs[3] = {Wh0, Wh1, Wh2};
    const unsigned short* Wls[3] = {Wl0, Wl1, Wl2};

    float c[2][8][4];
#pragma unroll
    for (int m = 0; m < 2; m++)
#pragma unroll
        for (int n = 0; n < 8; n++)
#pragma unroll
            for (int q = 0; q < 4; q++) c[m][n][q] = 0.f;

    // ldmatrix per-thread base addresses
    //   A x4: 16x16 tile, addr = &A[warp_m*32 + mt*16 + (lane&15)][(lane>>4)*8]
    //   B x4 (2 ntiles): addr = &B[nbase + ntp*16 + (lane&7) + ((lane>>4)*8)][((lane>>3)&1)*8]
    uint32_t a_off = (uint32_t)((warp_m * 32 + (lane & 15)) * ROWP + ((lane >> 4) << 3)) * 2;
    uint32_t b_off = (uint32_t)((warp_n * (N / 2) + (lane & 7) + ((lane >> 4) << 3)) * ROWP
                                + (((lane >> 3) & 1) << 3)) * 2;
    uint32_t aHi = sb + SA_HI + a_off, aLo = sb + SA_LO + a_off;
    uint32_t bHi = sb + SW_HI + b_off, bLo = sb + SW_LO + b_off;

    // A staging geometry: thread handles row = tid>>1, k half = (tid&1)*32
    int sr = tid >> 1;
    int skh = (tid & 1) << 5;

    for (int s = 0; s < nStages; s++) {
        const float* Abase = As[s];
        int lda = ldas[s], ko = kos[s];
        const unsigned short* wh = Whs[s];
        const unsigned short* wl = Wls[s];
        for (int kc = 0; kc < 128; kc += 64) {
            // --- stage W hi/lo: [n][64] slice, padded rows ---
            for (int i = tid; i < N * 8; i += 256) {
                int n = i >> 3, j = i & 7;
                const unsigned short* ph = wh + (size_t)n * 128 + kc + j * 8;
                const unsigned short* pl = wl + (size_t)n * 128 + kc + j * 8;
                *(uint4*)(smem + SW_HI + (n * ROWP + j * 8) * 2) = *(const uint4*)ph;
                *(uint4*)(smem + SW_LO + (n * ROWP + j * 8) * 2) = *(const uint4*)pl;
            }
            // --- stage A: load f32, split, store bf16 hi/lo ---
            {
                int grow = rowBase + sr; if (grow > M - 1) grow = M - 1;
                const float* arow = Abase + (size_t)grow * lda + ko + kc + skh;
#pragma unroll
                for (int q = 0; q < 4; q++) {
                    float4 fa = *(const float4*)(arow + q * 8);
                    float4 fb = *(const float4*)(arow + q * 8 + 4);
                    unsigned short h[8]; float lo[8];
                    splitbf(fa.x, h[0], lo[0]); splitbf(fa.y, h[1], lo[1]);
                    splitbf(fa.z, h[2], lo[2]); splitbf(fa.w, h[3], lo[3]);
                    splitbf(fb.x, h[4], lo[4]); splitbf(fb.y, h[5], lo[5]);
                    splitbf(fb.z, h[6], lo[6]); splitbf(fb.w, h[7], lo[7]);
                    uint4 hv, lv;
                    hv.x = (uint32_t)h[0] | ((uint32_t)h[1] << 16);
                    hv.y = (uint32_t)h[2] | ((uint32_t)h[3] << 16);
                    hv.z = (uint32_t)h[4] | ((uint32_t)h[5] << 16);
                    hv.w = (uint32_t)h[6] | ((uint32_t)h[7] << 16);
                    lv.x = (uint32_t)bf16of(lo[0]) | ((uint32_t)bf16of(lo[1]) << 16);
                    lv.y = (uint32_t)bf16of(lo[2]) | ((uint32_t)bf16of(lo[3]) << 16);
                    lv.z = (uint32_t)bf16of(lo[4]) | ((uint32_t)bf16of(lo[5]) << 16);
                    lv.w = (uint32_t)bf16of(lo[6]) | ((uint32_t)bf16of(lo[7]) << 16);
                    uint32_t off = (sr * ROWP + skh + q * 8) * 2;
                    *(uint4*)(smem + SA_HI + off) = hv;
                    *(uint4*)(smem + SA_LO + off) = lv;
                }
            }
            __syncthreads();

            // --- mma over 4 k16 steps; ldmatrix fragment loads ---
#pragma unroll
            for (int k16 = 0; k16 < 64; k16 += 16) {
                uint32_t ah[2][4], al[2][4];
#pragma unroll
                for (int mt = 0; mt < 2; mt++) {
                    uint32_t d = (uint32_t)(mt * 16 * ROWP + k16) * 2;
                    ldm_x4(ah[mt], aHi + d);
                    ldm_x4(al[mt], aLo + d);
                }
#pragma unroll
                for (int ntp = 0; ntp < NT / 2; ntp++) {
                    uint32_t d = (uint32_t)(ntp * 16 * ROWP + k16) * 2;
                    uint32_t bh[4], blo[4];
                    ldm_x4(bh,  bHi + d);
                    ldm_x4(blo, bLo + d);
#pragma unroll
                    for (int half = 0; half < 2; half++) {
                        int nt = ntp * 2 + half;
#pragma unroll
                        for (int mt = 0; mt < 2; mt++) {
                            mma16816(c[mt][nt], ah[mt], bh + half * 2);
                            mma16816(c[mt][nt], ah[mt], blo + half * 2);
                            mma16816(c[mt][nt], al[mt], bh + half * 2);
                        }
                    }
                }
            }
            __syncthreads();
        }
    }

    // --- epilogue ---
#pragma unroll
    for (int mt = 0; mt < 2; mt++) {
        int r0 = rowBase + warp_m * 32 + mt * 16 + g;
        int r1 = r0 + 8;
#pragma unroll
        for (int nt = 0; nt < NT; nt++) {
            int col = warp_n * (N / 2) + nt * 8 + t4 * 2;
            float bx = b0[col], by = b0[col + 1];
            if (b1) { bx += b1[col]; by += b1[col + 1]; }
            float2 o0, o1;
            o0.x = c[mt][nt][0] + bx; o0.y = c[mt][nt][1] + by;
            o1.x = c[mt][nt][2] + bx; o1.y = c[mt][nt][3] + by;
            if (relu) {
                o0.x = fmaxf(o0.x, 0.f); o0.y = fmaxf(o0.y, 0.f);
                o1.x = fmaxf(o1.x, 0.f); o1.y = fmaxf(o1.y, 0.f);
            }
            if (r0 < M) *(float2*)(Y + (size_t)r0 * N + col) = o0;
            if (r1 < M) *(float2*)(Y + (size_t)r1 * N + col) = o1;
        }
    }
}

// ---------------------------------------------------------------------------
// CSR build kernels
// ---------------------------------------------------------------------------
__global__ void zero_int_kernel(int* __restrict__ p, int n) {
    int stride = gridDim.x * blockDim.x;
    for (int i = blockIdx.x * blockDim.x + threadIdx.x; i < n; i += stride) p[i] = 0;
}
__global__ void hist_kernel(const int* __restrict__ dst, int* __restrict__ cnt, int n) {
    int i = blockIdx.x * blockDim.x + threadIdx.x;
    if (i < n) atomicAdd(&cnt[dst[i]], 1);
}
__global__ void scan_block_kernel(const int* __restrict__ in, int* __restrict__ out,
                                  int* __restrict__ bsums, int n) {
    __shared__ int sh[1024];
    int gid = blockIdx.x * 1024 + threadIdx.x;
    int v = (gid < n) ? in[gid] : 0;
    sh[threadIdx.x] = v;
    __syncthreads();
    for (int off = 1; off < 1024; off <<= 1) {
        int t = (threadIdx.x >= off) ? sh[threadIdx.x - off] : 0;
        __syncthreads();
        sh[threadIdx.x] += t;
        __syncthreads();
    }
    if (gid < n) out[gid] = sh[threadIdx.x] - v;
    if (threadIdx.x == 1023) bsums[blockIdx.x] = sh[1023];
}
__global__ void scan_partials_kernel(int* __restrict__ bsums, int nb) {
    __shared__ int sh[1024];
    int v = (threadIdx.x < nb) ? bsums[threadIdx.x] : 0;
    sh[threadIdx.x] = v;
    __syncthreads();
    for (int off = 1; off < 1024; off <<= 1) {
        int t = (threadIdx.x >= off) ? sh[threadIdx.x - off] : 0;
        __syncthreads();
        sh[threadIdx.x] += t;
        __syncthreads();
    }
    if (threadIdx.x < nb) bsums[threadIdx.x] = sh[threadIdx.x] - v;
}
__global__ void scan_add_kernel(int* __restrict__ rowptr, int* __restrict__ cnt,
                                const int* __restrict__ bsums, int n, int E) {
    int gid = blockIdx.x * 1024 + threadIdx.x;
    if (gid < n) {
        int r = rowptr[gid] + bsums[blockIdx.x];
        rowptr[gid] = r;
        cnt[gid] = r;
    }
    if (gid == 0) rowptr[n] = E;
}
__global__ void fill_csr_kernel(const int* __restrict__ src, const int* __restrict__ dst,
                                int* __restrict__ cnt, int* __restrict__ col, int n) {
    int i = blockIdx.x * blockDim.x + threadIdx.x;
    if (i < n) {
        int p = atomicAdd(&cnt[dst[i]], 1);
        col[p] = src[i];
    }
}

// ---------------------------------------------------------------------------
// Fused 3-way gather-mean
// ---------------------------------------------------------------------------
__device__ __forceinline__ void gather_one(const float4* __restrict__ feat,
                                           const int* __restrict__ rowptr,
                                           const int* __restrict__ col,
                                           float4* __restrict__ out, int node, int lane) {
    int e0 = __ldg(&rowptr[node]);
    int e1 = __ldg(&rowptr[node + 1]);
    float4 a0 = make_float4(0.f, 0.f, 0.f, 0.f);
    float4 a1 = make_float4(0.f, 0.f, 0.f, 0.f);
    int e = e0;
    for (; e + 3 < e1; e += 4) {
        int s0 = __ldg(&col[e]);
        int s1 = __ldg(&col[e + 1]);
        int s2 = __ldg(&col[e + 2]);
        int s3 = __ldg(&col[e + 3]);
        float4 v0 = feat[(size_t)s0 * 32 + lane];
        float4 v1 = feat[(size_t)s1 * 32 + lane];
        float4 v2 = feat[(size_t)s2 * 32 + lane];
        float4 v3 = feat[(size_t)s3 * 32 + lane];
        a0.x += v0.x + v1.x; a0.y += v0.y + v1.y; a0.z += v0.z + v1.z; a0.w += v0.w + v1.w;
        a1.x += v2.x + v3.x; a1.y += v2.y + v3.y; a1.z += v2.z + v3.z; a1.w += v2.w + v3.w;
    }
    for (; e < e1; e++) {
        int s = __ldg(&col[e]);
        float4 v = feat[(size_t)s * 32 + lane];
        a0.x += v.x; a0.y += v.y; a0.z += v.z; a0.w += v.w;
    }
    float inv = 1.0f / fmaxf((float)(e1 - e0), 1.0f);
    float4 o;
    o.x = (a0.x + a1.x) * inv; o.y = (a0.y + a1.y) * inv;
    o.z = (a0.z + a1.z) * inv; o.w = (a0.w + a1.w) * inv;
    out[(size_t)node * 32 + lane] = o;
}

__global__ void gather3_kernel(const float4* __restrict__ featA, const float4* __restrict__ featP,
                               const int* __restrict__ rp1, const int* __restrict__ c1, float4* __restrict__ mp1,
                               const int* __restrict__ rp3, const int* __restrict__ c3, float4* __restrict__ mp2,
                               const int* __restrict__ rp2, const int* __restrict__ c2, float4* __restrict__ ma) {
    int w = (blockIdx.x * blockDim.x + threadIdx.x) >> 5;
    int lane = threadIdx.x & 31;
    if (w < NPAPER) {
        gather_one(featA, rp1, c1, mp1, w, lane);
    } else if (w < 2 * NPAPER) {
        gather_one(featP, rp3, c3, mp2, w - NPAPER, lane);
    } else if (w < 2 * NPAPER + NAUTHOR) {
        gather_one(featP, rp2, c2, ma, w - 2 * NPAPER, lane);
    }
}

// ---------------------------------------------------------------------------
// Host helpers
// ---------------------------------------------------------------------------
static void build_csr(const int* src, const int* dst, int ndst,
                      int* rowptr, int* col, int* cnt, int* bsums) {
    int nb = (ndst + 1023) / 1024;
    zero_int_kernel<<<256, 256>>>(cnt, ndst);
    hist_kernel<<<(NEDGE + 255) / 256, 256>>>(dst, cnt, NEDGE);
    scan_block_kernel<<<nb, 1024>>>(cnt, rowptr, bsums, ndst);
    scan_partials_kernel<<<1, 1024>>>(bsums, nb);
    scan_add_kernel<<<nb, 1024>>>(rowptr, cnt, bsums, ndst, NEDGE);
    fill_csr_kernel<<<(NEDGE + 255) / 256, 256>>>(src, dst, cnt, col, NEDGE);
}

extern "C" void kernel_launch(void* const* d_in, const int* in_sizes, int n_in,
                              void* d_out, int out_size) {
    const float* x_paper  = (const float*)d_in[0];
    const float* x_author = (const float*)d_in[1];
    const float* lin_p_w  = (const float*)d_in[2];
    const float* lin_p_b  = (const float*)d_in[3];
    const float* lin_a_w  = (const float*)d_in[4];
    const float* lin_a_b  = (const float*)d_in[5];
    const float* Wl       = (const float*)d_in[6];
    const float* bl       = (const float*)d_in[7];
    const float* Wr       = (const float*)d_in[8];
    const float* lin_w    = (const float*)d_in[9];
    const float* lin_b    = (const float*)d_in[10];
    const int* a2p_src = (const int*)d_in[11];
    const int* a2p_dst = (const int*)d_in[12];
    const int* p2a_src = (const int*)d_in[13];
    const int* p2a_dst = (const int*)d_in[14];
    const int* p2p_src = (const int*)d_in[15];
    const int* p2p_dst = (const int*)d_in[16];
    float* out = (float*)d_out;

    float *yp0, *yp1, *ya0, *ya1, *mp1, *mp2, *ma;
    int *rp1, *rp2, *rp3, *c1, *c2, *c3, *cnt, *bsums;
    unsigned short *wih, *wil;
    cudaGetSymbolAddress((void**)&yp0, g_yp0);
    cudaGetSymbolAddress((void**)&yp1, g_yp1);
    cudaGetSymbolAddress((void**)&ya0, g_ya0);
    cudaGetSymbolAddress((void**)&ya1, g_ya1);
    cudaGetSymbolAddress((void**)&mp1, g_mp1);
    cudaGetSymbolAddress((void**)&mp2, g_mp2);
    cudaGetSymbolAddress((void**)&ma,  g_ma);
    cudaGetSymbolAddress((void**)&rp1, g_rp_a2p);
    cudaGetSymbolAddress((void**)&rp2, g_rp_p2a);
    cudaGetSymbolAddress((void**)&rp3, g_rp_p2p);
    cudaGetSymbolAddress((void**)&c1,  g_col_a2p);
    cudaGetSymbolAddress((void**)&c2,  g_col_p2a);
    cudaGetSymbolAddress((void**)&c3,  g_col_p2p);
    cudaGetSymbolAddress((void**)&cnt, g_cnt);
    cudaGetSymbolAddress((void**)&bsums, g_bsums);
    cudaGetSymbolAddress((void**)&wih, g_wih);
    cudaGetSymbolAddress((void**)&wil, g_wil);

    cudaFuncSetAttribute(gemm_mma<128>, cudaFuncAttributeMaxDynamicSharedMemorySize, SMEM_TOTAL);
    cudaFuncSetAttribute(gemm_mma<64>,  cudaFuncAttributeMaxDynamicSharedMemorySize, SMEM_TOTAL);

    const int GP = (NPAPER + 127) / 128;
    const int GA = (NAUTHOR + 127) / 128;

    // 1: weight prep
    prep_w_kernel<<<14, 256>>>(lin_p_w, lin_a_w, Wl, Wr, lin_w, wih, wil);
    // 2: first CSR zero
    zero_int_kernel<<<256, 256>>>(cnt, NPAPER);
    // 3: paper projection (K=256 -> 2 stages), relu
    gemm_mma<128><<<GP, 256, SMEM_TOTAL>>>(
        x_paper, 256, 0,   wih + 0 * IMG, wil + 0 * IMG,
        x_paper, 256, 128, wih + 1 * IMG, wil + 1 * IMG,
        nullptr, 0, 0, nullptr, nullptr,
        2, NPAPER, lin_p_b, nullptr, yp0, 1);
    // 4: author projection (ncu capture slot), relu
    gemm_mma<128><<<GA, 256, SMEM_TOTAL>>>(
        x_author, 128, 0, wih + 2 * IMG, wil + 2 * IMG,
        nullptr, 0, 0, nullptr, nullptr,
        nullptr, 0, 0, nullptr, nullptr,
        1, NAUTHOR, lin_a_b, nullptr, ya0, 1);

    // finish CSR a2p (cnt already zeroed)
    {
        int nb = (NPAPER + 1023) / 1024;
        hist_kernel<<<(NEDGE + 255) / 256, 256>>>(a2p_dst, cnt, NEDGE);
        scan_block_kernel<<<nb, 1024>>>(cnt, rp1, bsums, NPAPER);
        scan_partials_kernel<<<1, 1024>>>(bsums, nb);
        scan_add_kernel<<<nb, 1024>>>(rp1, cnt, bsums, NPAPER, NEDGE);
        fill_csr_kernel<<<(NEDGE + 255) / 256, 256>>>(a2p_src, a2p_dst, cnt, c1, NEDGE);
    }
    build_csr(p2a_src, p2a_dst, NAUTHOR, rp2, c2, cnt, bsums);
    build_csr(p2p_src, p2p_dst, NPAPER,  rp3, c3, cnt, bsums);

    float *ypc = yp0, *ypn = yp1, *yac = ya0, *yan = ya1;
    const int GG = ((2 * NPAPER + NAUTHOR) * 32 + 255) / 256;

    for (int l = 0; l < 2; l++) {
        gather3_kernel<<<GG, 256>>>((const float4*)yac, (const float4*)ypc,
                                    rp1, c1, (float4*)mp1,
                                    rp3, c3, (float4*)mp2,
                                    rp2, c2, (float4*)ma);

        // new_p = m_a2p@Wl[l,0] + m_p2p@Wl[l,2] + yp@(Wr[l,0]+Wr[l,2]) + biases
        gemm_mma<128><<<GP, 256, SMEM_TOTAL>>>(
            mp1, 128, 0, wih + (3 + l * 3 + 0) * IMG, wil + (3 + l * 3 + 0) * IMG,
            mp2, 128, 0, wih + (3 + l * 3 + 2) * IMG, wil + (3 + l * 3 + 2) * IMG,
            ypc, 128, 0, wih + (9 + l) * IMG,          wil + (9 + l) * IMG,
            3, NPAPER,
            bl + (size_t)(l * 3 + 0) * HD, bl + (size_t)(l * 3 + 2) * HD, ypn, 0);

        // new_a = m_p2a@Wl[l,1] + ya@Wr[l,1] + bl[l,1]
        gemm_mma<128><<<GA, 256, SMEM_TOTAL>>>(
            ma,  128, 0, wih + (3 + l * 3 + 1) * IMG, wil + (3 + l * 3 + 1) * IMG,
            yac, 128, 0, wih + (11 + l) * IMG,         wil + (11 + l) * IMG,
            nullptr, 0, 0, nullptr, nullptr,
            2, NAUTHOR,
            bl + (size_t)(l * 3 + 1) * HD, nullptr, yan, 0);

        float* t;
        t = ypc; ypc = ypn; ypn = t;
        t = yac; yac = yan; yan = t;
    }

    // final classifier (N=64)
    gemm_mma<64><<<GP, 256, SMEM_TOTAL>>>(
        ypc, 128, 0, wih + 13 * IMG, wil + 13 * IMG,
        nullptr, 0, 0, nullptr, nullptr,
        nullptr, 0, 0, nullptr, nullptr,
        1, NPAPER, lin_b, nullptr, out, 0);
}